// round 1
// baseline (speedup 1.0000x reference)
#include <cuda_runtime.h>
#include <cstdint>

#define N_NODES 15279
#define E_EDGES 488928
#define IN_CH   1024
#define N_HID   512
#define N_CLASS 16
#define EMB_DIM 128

// ---------------- scratch (static device memory; no allocations) -------------
__device__ float g_h0[(size_t)N_NODES * IN_CH];    // 62.6 MB embed+relu
__device__ float g_t1[(size_t)N_NODES * N_HID];    // 31.3 MB h0@W1
__device__ float g_h1[(size_t)N_NODES * N_HID];    // 31.3 MB relu(spmm+b1)
__device__ float g_t2[(size_t)N_NODES * N_CLASS];  //  1.0 MB h1@W2
__device__ int   g_counts[N_NODES];
__device__ int   g_rowptr[N_NODES + 1];
__device__ int   g_cursor[N_NODES];
__device__ int   g_ecol[E_EDGES];
__device__ float g_eval[E_EDGES];
__device__ int   g_x64flag;

// ---------------- dtype detection for x (int32 vs int64) ---------------------
__global__ void detect_kernel(const int* x32, int n_pairs) {
    __shared__ int any;
    if (threadIdx.x == 0) any = 0;
    __syncthreads();
    int local = 0;
    for (int i = threadIdx.x; i < n_pairs; i += blockDim.x)
        if (x32[2 * i + 1] != 0) local = 1;
    if (local) atomicOr(&any, 1);
    __syncthreads();
    if (threadIdx.x == 0) g_x64flag = (any == 0);  // all-zero high words => int64
}

// ---------------- embedding lookup + relu -> g_h0 ----------------------------
// grid = N_NODES, block = 256 (8 warps, warp j = slot j, lane = float4 chunk)
__global__ void embed_kernel(const int* x32, const float* __restrict__ emb) {
    int n = blockIdx.x;
    int w = threadIdx.x >> 5, lane = threadIdx.x & 31;
    int idx;
    if (g_x64flag) idx = x32[2 * (n * 8 + w)];   // little-endian low word
    else           idx = x32[n * 8 + w];
    float4 v = ((const float4*)(emb + (size_t)idx * EMB_DIM))[lane];
    v.x = fmaxf(v.x, 0.f); v.y = fmaxf(v.y, 0.f);
    v.z = fmaxf(v.z, 0.f); v.w = fmaxf(v.w, 0.f);
    ((float4*)(g_h0 + (size_t)n * IN_CH + w * EMB_DIM))[lane] = v;
}

// ---------------- GEMM1: g_t1 = g_h0[M,1024] @ W1[1024,512] ------------------
#define BM 128
#define BN 64
#define BK 16
__global__ __launch_bounds__(256) void gemm1_kernel(const float* __restrict__ B) {
    const int M = N_NODES, K = IN_CH, N = N_HID;
    __shared__ float As[BK][BM + 1];   // +1 pad: conflict-free transposed stores
    __shared__ float Bs[BK][BN];
    int bm = blockIdx.y * BM, bn = blockIdx.x * BN;
    int tid = threadIdx.x;
    int tx = tid & 15, ty = tid >> 4;
    float acc[8][4];
#pragma unroll
    for (int i = 0; i < 8; i++)
#pragma unroll
        for (int j = 0; j < 4; j++) acc[i][j] = 0.f;

    for (int k0 = 0; k0 < K; k0 += BK) {
        // load A tile: 128x16 = 512 float4, 2 per thread, transpose into As
#pragma unroll
        for (int l = 0; l < 2; l++) {
            int i = tid + l * 256;          // 0..511
            int r = i >> 2;                 // tile row 0..127
            int kk = (i & 3) * 4;           // 0,4,8,12
            float4 v = make_float4(0.f, 0.f, 0.f, 0.f);
            int gm = bm + r;
            if (gm < M)
                v = *(const float4*)(g_h0 + (size_t)gm * K + k0 + kk);
            As[kk + 0][r] = v.x; As[kk + 1][r] = v.y;
            As[kk + 2][r] = v.z; As[kk + 3][r] = v.w;
        }
        // load B tile: 16x64 = 256 float4, 1 per thread
        {
            int r = tid >> 4;
            int c = (tid & 15) * 4;
            float4 v = *(const float4*)(B + (size_t)(k0 + r) * N + bn + c);
            *(float4*)(&Bs[r][c]) = v;
        }
        __syncthreads();
#pragma unroll
        for (int k = 0; k < BK; k++) {
            float a[8], b[4];
#pragma unroll
            for (int i = 0; i < 8; i++) a[i] = As[k][ty + i * 16];
#pragma unroll
            for (int j = 0; j < 4; j++) b[j] = Bs[k][tx + j * 16];
#pragma unroll
            for (int i = 0; i < 8; i++)
#pragma unroll
                for (int j = 0; j < 4; j++) acc[i][j] += a[i] * b[j];
        }
        __syncthreads();
    }
#pragma unroll
    for (int i = 0; i < 8; i++) {
        int gm = bm + ty + i * 16;
        if (gm < M) {
#pragma unroll
            for (int j = 0; j < 4; j++)
                g_t1[(size_t)gm * N + bn + tx + j * 16] = acc[i][j];
        }
    }
}

// ---------------- CSR build --------------------------------------------------
__global__ void zero_counts_kernel() {
    int i = blockIdx.x * blockDim.x + threadIdx.x;
    if (i < N_NODES) g_counts[i] = 0;
}

__global__ void hist_kernel(const int* __restrict__ rows, int E) {
    int i = blockIdx.x * blockDim.x + threadIdx.x;
    if (i < E) atomicAdd(&g_counts[rows[i]], 1);
}

// single-block 1024-thread exclusive scan -> g_rowptr
__global__ void scan_kernel() {
    __shared__ int s[1024];
    int tid = threadIdx.x;
    int carry = 0;
    if (tid == 0) g_rowptr[0] = 0;
    for (int base = 0; base < N_NODES; base += 1024) {
        int v = (base + tid < N_NODES) ? g_counts[base + tid] : 0;
        s[tid] = v;
        __syncthreads();
        for (int off = 1; off < 1024; off <<= 1) {
            int t = (tid >= off) ? s[tid - off] : 0;
            __syncthreads();
            s[tid] += t;
            __syncthreads();
        }
        if (base + tid < N_NODES) g_rowptr[base + tid + 1] = carry + s[tid];
        carry += s[1023];
        __syncthreads();
    }
}

__global__ void cursor_kernel() {
    int i = blockIdx.x * blockDim.x + threadIdx.x;
    if (i < N_NODES) g_cursor[i] = g_rowptr[i];
}

__global__ void scatter_kernel(const int* __restrict__ rows, const int* __restrict__ cols,
                               const float* __restrict__ vals, int E) {
    int i = blockIdx.x * blockDim.x + threadIdx.x;
    if (i < E) {
        int r = rows[i];
        int p = atomicAdd(&g_cursor[r], 1);
        g_ecol[p] = cols[i];
        g_eval[p] = vals[i];
    }
}

// ---------------- SpMM1 (+b1, relu): g_h1 = relu(A @ g_t1 + b1) --------------
// grid = N_NODES rows, block = 128 threads, each thread = one float4 of 512
__global__ __launch_bounds__(128) void spmm1_kernel(const float* __restrict__ b1) {
    int r = blockIdx.x;
    int tid = threadIdx.x;
    int s = g_rowptr[r], e = g_rowptr[r + 1];
    float4 acc = make_float4(0.f, 0.f, 0.f, 0.f);
    for (int i = s; i < e; i++) {
        int   c = g_ecol[i];
        float v = g_eval[i];
        float4 t = __ldg((const float4*)(g_t1 + (size_t)c * N_HID) + tid);
        acc.x += v * t.x; acc.y += v * t.y; acc.z += v * t.z; acc.w += v * t.w;
    }
    float4 bb = ((const float4*)b1)[tid];
    acc.x = fmaxf(acc.x + bb.x, 0.f);
    acc.y = fmaxf(acc.y + bb.y, 0.f);
    acc.z = fmaxf(acc.z + bb.z, 0.f);
    acc.w = fmaxf(acc.w + bb.w, 0.f);
    ((float4*)(g_h1 + (size_t)r * N_HID))[tid] = acc;
}

// ---------------- GEMM2: g_t2 = g_h1[M,512] @ W2[512,16] ---------------------
// block = 256 = 16 rows x 16 cols; W2 staged in shared
__global__ __launch_bounds__(256) void gemm2_kernel(const float* __restrict__ W2) {
    __shared__ float Ws[N_HID * N_CLASS];  // 32 KB
    for (int i = threadIdx.x; i < N_HID * N_CLASS; i += blockDim.x) Ws[i] = W2[i];
    __syncthreads();
    int row = blockIdx.x * 16 + (threadIdx.x >> 4);
    int c = threadIdx.x & 15;
    if (row >= N_NODES) return;
    const float4* a4 = (const float4*)(g_h1 + (size_t)row * N_HID);
    float acc = 0.f;
#pragma unroll 4
    for (int k = 0; k < N_HID / 4; k++) {
        float4 a = a4[k];
        acc += a.x * Ws[(4 * k + 0) * N_CLASS + c];
        acc += a.y * Ws[(4 * k + 1) * N_CLASS + c];
        acc += a.z * Ws[(4 * k + 2) * N_CLASS + c];
        acc += a.w * Ws[(4 * k + 3) * N_CLASS + c];
    }
    g_t2[(size_t)row * N_CLASS + c] = acc;
}

// ---------------- SpMM2 (+b2): out = A @ g_t2 + b2 ---------------------------
// one warp per row; lanes 0..15 = class channels
__global__ void spmm2_kernel(const float* __restrict__ b2, float* __restrict__ out) {
    int w = (blockIdx.x * blockDim.x + threadIdx.x) >> 5;
    int lane = threadIdx.x & 31;
    if (w >= N_NODES) return;
    int s = g_rowptr[w], e = g_rowptr[w + 1];
    float acc = 0.f;
    for (int i = s; i < e; i++) {
        int   c = g_ecol[i];
        float v = g_eval[i];
        if (lane < N_CLASS) acc += v * __ldg(g_t2 + (size_t)c * N_CLASS + lane);
    }
    if (lane < N_CLASS) out[(size_t)w * N_CLASS + lane] = acc + b2[lane];
}

// ---------------- launch -----------------------------------------------------
extern "C" void kernel_launch(void* const* d_in, const int* in_sizes, int n_in,
                              void* d_out, int out_size) {
    const int*   x    = (const int*)d_in[0];   // int32 or int64 (auto-detected)
    const int*   rows = (const int*)d_in[1];
    const int*   cols = (const int*)d_in[2];
    const float* vals = (const float*)d_in[3];
    const float* emb  = (const float*)d_in[4];
    const float* W1   = (const float*)d_in[5];
    const float* b1   = (const float*)d_in[6];
    const float* W2   = (const float*)d_in[7];
    const float* b2   = (const float*)d_in[8];
    float* out = (float*)d_out;
    int E = in_sizes[1];

    detect_kernel<<<1, 256>>>(x, 512);
    embed_kernel<<<N_NODES, 256>>>(x, emb);
    gemm1_kernel<<<dim3(N_HID / BN, (N_NODES + BM - 1) / BM), 256>>>(W1);

    zero_counts_kernel<<<(N_NODES + 255) / 256, 256>>>();
    hist_kernel<<<(E + 255) / 256, 256>>>(rows, E);
    scan_kernel<<<1, 1024>>>();
    cursor_kernel<<<(N_NODES + 255) / 256, 256>>>();
    scatter_kernel<<<(E + 255) / 256, 256>>>(rows, cols, vals, E);

    spmm1_kernel<<<N_NODES, 128>>>(b1);
    gemm2_kernel<<<(N_NODES + 15) / 16, 256>>>(W2);
    spmm2_kernel<<<(N_NODES * 32 + 255) / 256, 256>>>(b2, out);
}

// round 5
// speedup vs baseline: 2.1110x; 2.1110x over previous
#include <cuda_runtime.h>
#include <cuda_bf16.h>
#include <cstdint>

#define N_NODES 15279
#define M_PAD   15360
#define E_EDGES 488928
#define IN_CH   1024
#define N_HID   512
#define N_CLASS 16
#define EMB_DIM 128

// ---------------- scratch (static device memory; no allocations) -------------
__device__ __nv_bfloat16 g_ahi[(size_t)M_PAD * IN_CH];   // 31.5 MB (zero-init pad rows)
__device__ __nv_bfloat16 g_alo[(size_t)M_PAD * IN_CH];   // 31.5 MB
__device__ __nv_bfloat16 g_bhi[(size_t)N_HID * IN_CH];   // 1 MB  (W1^T hi)
__device__ __nv_bfloat16 g_blo[(size_t)N_HID * IN_CH];   // 1 MB  (W1^T lo)
__device__ float g_t1[(size_t)N_NODES * N_HID];          // 31.3 MB h0@W1
__device__ float g_h1[(size_t)N_NODES * N_HID];          // 31.3 MB relu(spmm+b1)
__device__ float g_t2[(size_t)N_NODES * N_CLASS];        //  1.0 MB h1@W2
__device__ int   g_counts[N_NODES];
__device__ int   g_rowptr[N_NODES + 1];
__device__ int   g_cursor[N_NODES];
__device__ int   g_ecol[E_EDGES];
__device__ float g_eval[E_EDGES];
__device__ int   g_x64flag;

// ---------------- PTX helpers (sm_80+ features only; no tcgen05) -------------
static __device__ __forceinline__ uint32_t s2u(const void* p) {
    uint32_t a;
    asm("{ .reg .u64 t; cvta.to.shared.u64 t, %1; cvt.u32.u64 %0, t; }" : "=r"(a) : "l"(p));
    return a;
}
static __device__ __forceinline__ void cp16(uint32_t dst, const void* src) {
    asm volatile("cp.async.cg.shared.global [%0], [%1], 16;" :: "r"(dst), "l"(src));
}
static __device__ __forceinline__ void cp_commit() {
    asm volatile("cp.async.commit_group;" ::: "memory");
}
static __device__ __forceinline__ void cp_wait1() {
    asm volatile("cp.async.wait_group 1;" ::: "memory");
}
static __device__ __forceinline__ void ldsm4(uint32_t* r, uint32_t a) {
    asm volatile("ldmatrix.sync.aligned.m8n8.x4.shared.b16 {%0,%1,%2,%3}, [%4];"
                 : "=r"(r[0]), "=r"(r[1]), "=r"(r[2]), "=r"(r[3]) : "r"(a));
}
static __device__ __forceinline__ void mma16816(float* d, const uint32_t* a, const uint32_t* b) {
    asm volatile(
        "mma.sync.aligned.m16n8k16.row.col.f32.bf16.bf16.f32 "
        "{%0,%1,%2,%3}, {%4,%5,%6,%7}, {%8,%9}, {%0,%1,%2,%3};"
        : "+f"(d[0]), "+f"(d[1]), "+f"(d[2]), "+f"(d[3])
        : "r"(a[0]), "r"(a[1]), "r"(a[2]), "r"(a[3]), "r"(b[0]), "r"(b[1]));
}

// ---------------- dtype detection for x (int32 vs int64) ---------------------
__global__ void detect_kernel(const int* x32, int n_pairs) {
    __shared__ int any;
    if (threadIdx.x == 0) any = 0;
    __syncthreads();
    int local = 0;
    for (int i = threadIdx.x; i < n_pairs; i += blockDim.x)
        if (x32[2 * i + 1] != 0) local = 1;
    if (local) atomicOr(&any, 1);
    __syncthreads();
    if (threadIdx.x == 0) g_x64flag = (any == 0);
}

// ---------------- embedding lookup + relu -> bf16 hi/lo ----------------------
__global__ void embed_kernel(const int* x32, const float* __restrict__ emb) {
    int n = blockIdx.x;
    int w = threadIdx.x >> 5, lane = threadIdx.x & 31;
    int idx;
    if (g_x64flag) idx = x32[2 * (n * 8 + w)];
    else           idx = x32[n * 8 + w];
    float4 v = ((const float4*)(emb + (size_t)idx * EMB_DIM))[lane];
    float f[4] = {fmaxf(v.x, 0.f), fmaxf(v.y, 0.f), fmaxf(v.z, 0.f), fmaxf(v.w, 0.f)};
    __nv_bfloat16 hi[4], lo[4];
#pragma unroll
    for (int i = 0; i < 4; i++) {
        hi[i] = __float2bfloat16(f[i]);
        lo[i] = __float2bfloat16(f[i] - __bfloat162float(hi[i]));
    }
    size_t off = (size_t)n * IN_CH + w * EMB_DIM + lane * 4;
    *(uint2*)(g_ahi + off) = *(uint2*)hi;
    *(uint2*)(g_alo + off) = *(uint2*)lo;
}

// W1 [K=1024, N=512] fp32 -> B [N=512, K=1024] bf16 hi/lo (transposed)
__global__ void convw1_kernel(const float* __restrict__ W1) {
    int i = blockIdx.x * blockDim.x + threadIdx.x;
    if (i >= N_HID * IN_CH / 2) return;
    int n = i / (IN_CH / 2);
    int k2 = (i % (IN_CH / 2)) * 2;
    float v0 = __ldg(W1 + (size_t)k2 * N_HID + n);
    float v1 = __ldg(W1 + (size_t)(k2 + 1) * N_HID + n);
    __nv_bfloat16 h0 = __float2bfloat16(v0), h1 = __float2bfloat16(v1);
    __nv_bfloat16 l0 = __float2bfloat16(v0 - __bfloat162float(h0));
    __nv_bfloat16 l1 = __float2bfloat16(v1 - __bfloat162float(h1));
    __nv_bfloat16 ph[2] = {h0, h1}, pl[2] = {l0, l1};
    *(uint32_t*)(g_bhi + (size_t)n * IN_CH + k2) = *(uint32_t*)ph;
    *(uint32_t*)(g_blo + (size_t)n * IN_CH + k2) = *(uint32_t*)pl;
}

// ---------------- GEMM1 via mma.sync bf16 hi/lo: t1 = A @ B^T ----------------
// block tile 128x128, BK=64, 8 warps (4Mx2N), warp tile 32x64,
// SW128-swizzled smem, 2-stage cp.async pipeline.
#define GTILE 16384                    // one operand part per stage: 128 x 64 bf16
#define GSTAGE (4 * GTILE)             // Ahi, Alo, Bhi, Blo
#define GEMM_SMEM (2 * GSTAGE)         // 131072

static __device__ __forceinline__ void gemm_issue(uint32_t sb, int s, int k0,
                                                  int bm, int bn, int tid) {
    const __nv_bfloat16* srcs[4] = {g_ahi, g_alo, g_bhi, g_blo};
    uint32_t stage = sb + s * GSTAGE;
#pragma unroll
    for (int arr = 0; arr < 4; arr++) {
        const __nv_bfloat16* src = srcs[arr];
        int rowoff = (arr < 2) ? bm : bn;
#pragma unroll
        for (int l = 0; l < 4; l++) {
            int unit = tid + l * 256;
            int r = unit >> 3, u = unit & 7;
            uint32_t bo = (r << 7) | (u << 4);
            uint32_t sw = bo ^ ((bo >> 3) & 0x70);
            cp16(stage + arr * GTILE + sw,
                 src + (size_t)(rowoff + r) * IN_CH + k0 + u * 8);
        }
    }
    cp_commit();
}

__global__ void __launch_bounds__(256, 1) gemm1_mma_kernel() {
    extern __shared__ char smem[];
    uint32_t sb = s2u(smem);
    const int tid = threadIdx.x;
    const int wid = tid >> 5, lane = tid & 31;
    const int bm = blockIdx.y * 128, bn = blockIdx.x * 128;
    const int warp_m = (wid & 3) * 32;
    const int warp_n = (wid >> 2) * 64;

    float acc[2][8][4];
#pragma unroll
    for (int mi = 0; mi < 2; mi++)
#pragma unroll
        for (int nj = 0; nj < 8; nj++)
#pragma unroll
            for (int q = 0; q < 4; q++) acc[mi][nj][q] = 0.f;

    gemm_issue(sb, 0, 0, bm, bn, tid);
    gemm_issue(sb, 1, 64, bm, bn, tid);

    const int NCHUNK = IN_CH / 64;   // 16
    for (int c = 0; c < NCHUNK; c++) {
        cp_wait1();
        __syncthreads();
        uint32_t stage = sb + (c & 1) * GSTAGE;
#pragma unroll
        for (int kk = 0; kk < 4; kk++) {
            // A fragments (hi/lo), 2 m-subtiles of 16
            uint32_t ahi[2][4], alo[2][4];
#pragma unroll
            for (int mi = 0; mi < 2; mi++) {
                int row = warp_m + mi * 16 + ((lane >> 3) & 1) * 8 + (lane & 7);
                int unit = kk * 2 + (lane >> 4);
                uint32_t bo = (row << 7) | (unit << 4);
                uint32_t sw = bo ^ ((bo >> 3) & 0x70);
                ldsm4(ahi[mi], stage + 0 * GTILE + sw);
                ldsm4(alo[mi], stage + 1 * GTILE + sw);
            }
            // B fragments (hi/lo), 8 n8 chunks loaded as 4 x4-ldmatrix
            uint32_t bhi[8][2], blo[8][2];
#pragma unroll
            for (int p = 0; p < 4; p++) {
                int row = warp_n + p * 16 + (lane >> 4) * 8 + (lane & 7);
                int unit = kk * 2 + ((lane >> 3) & 1);
                uint32_t bo = (row << 7) | (unit << 4);
                uint32_t sw = bo ^ ((bo >> 3) & 0x70);
                uint32_t t[4];
                ldsm4(t, stage + 2 * GTILE + sw);
                bhi[2 * p][0] = t[0]; bhi[2 * p][1] = t[1];
                bhi[2 * p + 1][0] = t[2]; bhi[2 * p + 1][1] = t[3];
                ldsm4(t, stage + 3 * GTILE + sw);
                blo[2 * p][0] = t[0]; blo[2 * p][1] = t[1];
                blo[2 * p + 1][0] = t[2]; blo[2 * p + 1][1] = t[3];
            }
#pragma unroll
            for (int mi = 0; mi < 2; mi++)
#pragma unroll
                for (int nj = 0; nj < 8; nj++) {
                    mma16816(acc[mi][nj], ahi[mi], bhi[nj]);
                    mma16816(acc[mi][nj], ahi[mi], blo[nj]);
                    mma16816(acc[mi][nj], alo[mi], bhi[nj]);
                }
        }
        __syncthreads();
        if (c + 2 < NCHUNK) gemm_issue(sb, c & 1, (c + 2) * 64, bm, bn, tid);
    }

    // epilogue: c-frag rows l/4 and l/4+8, cols 2*(l%4)
#pragma unroll
    for (int mi = 0; mi < 2; mi++) {
        int r0 = bm + warp_m + mi * 16 + (lane >> 2);
        int r1 = r0 + 8;
#pragma unroll
        for (int nj = 0; nj < 8; nj++) {
            int col = bn + warp_n + nj * 8 + (lane & 3) * 2;
            if (r0 < N_NODES)
                *(float2*)(g_t1 + (size_t)r0 * N_HID + col) = make_float2(acc[mi][nj][0], acc[mi][nj][1]);
            if (r1 < N_NODES)
                *(float2*)(g_t1 + (size_t)r1 * N_HID + col) = make_float2(acc[mi][nj][2], acc[mi][nj][3]);
        }
    }
}

// ---------------- CSR build --------------------------------------------------
__global__ void zero_counts_kernel() {
    int i = blockIdx.x * blockDim.x + threadIdx.x;
    if (i < N_NODES) g_counts[i] = 0;
}
__global__ void hist_kernel(const int* __restrict__ rows, int E) {
    int i = blockIdx.x * blockDim.x + threadIdx.x;
    if (i < E) atomicAdd(&g_counts[rows[i]], 1);
}
__global__ void scan_kernel() {
    __shared__ int s[1024];
    int tid = threadIdx.x;
    int carry = 0;
    if (tid == 0) g_rowptr[0] = 0;
    for (int base = 0; base < N_NODES; base += 1024) {
        int v = (base + tid < N_NODES) ? g_counts[base + tid] : 0;
        s[tid] = v;
        __syncthreads();
        for (int off = 1; off < 1024; off <<= 1) {
            int t = (tid >= off) ? s[tid - off] : 0;
            __syncthreads();
            s[tid] += t;
            __syncthreads();
        }
        if (base + tid < N_NODES) g_rowptr[base + tid + 1] = carry + s[tid];
        carry += s[1023];
        __syncthreads();
    }
}
__global__ void cursor_kernel() {
    int i = blockIdx.x * blockDim.x + threadIdx.x;
    if (i < N_NODES) g_cursor[i] = g_rowptr[i];
}
__global__ void scatter_kernel(const int* __restrict__ rows, const int* __restrict__ cols,
                               const float* __restrict__ vals, int E) {
    int i = blockIdx.x * blockDim.x + threadIdx.x;
    if (i < E) {
        int r = rows[i];
        int p = atomicAdd(&g_cursor[r], 1);
        g_ecol[p] = cols[i];
        g_eval[p] = vals[i];
    }
}

// ---------------- SpMM1 (+b1, relu): g_h1 = relu(A @ g_t1 + b1) --------------
__global__ __launch_bounds__(128) void spmm1_kernel(const float* __restrict__ b1) {
    int r = blockIdx.x;
    int tid = threadIdx.x;
    int s = g_rowptr[r], e = g_rowptr[r + 1];
    float4 acc = make_float4(0.f, 0.f, 0.f, 0.f);
    for (int i = s; i < e; i++) {
        int   c = g_ecol[i];
        float v = g_eval[i];
        float4 t = __ldg((const float4*)(g_t1 + (size_t)c * N_HID) + tid);
        acc.x += v * t.x; acc.y += v * t.y; acc.z += v * t.z; acc.w += v * t.w;
    }
    float4 bb = ((const float4*)b1)[tid];
    acc.x = fmaxf(acc.x + bb.x, 0.f);
    acc.y = fmaxf(acc.y + bb.y, 0.f);
    acc.z = fmaxf(acc.z + bb.z, 0.f);
    acc.w = fmaxf(acc.w + bb.w, 0.f);
    ((float4*)(g_h1 + (size_t)r * N_HID))[tid] = acc;
}

// ---------------- GEMM2: g_t2 = g_h1[M,512] @ W2[512,16] ---------------------
__global__ __launch_bounds__(256) void gemm2_kernel(const float* __restrict__ W2) {
    __shared__ float Ws[N_HID * N_CLASS];
    for (int i = threadIdx.x; i < N_HID * N_CLASS; i += blockDim.x) Ws[i] = W2[i];
    __syncthreads();
    int row = blockIdx.x * 16 + (threadIdx.x >> 4);
    int c = threadIdx.x & 15;
    if (row >= N_NODES) return;
    const float4* a4 = (const float4*)(g_h1 + (size_t)row * N_HID);
    float acc = 0.f;
#pragma unroll 4
    for (int k = 0; k < N_HID / 4; k++) {
        float4 a = a4[k];
        acc += a.x * Ws[(4 * k + 0) * N_CLASS + c];
        acc += a.y * Ws[(4 * k + 1) * N_CLASS + c];
        acc += a.z * Ws[(4 * k + 2) * N_CLASS + c];
        acc += a.w * Ws[(4 * k + 3) * N_CLASS + c];
    }
    g_t2[(size_t)row * N_CLASS + c] = acc;
}

// ---------------- SpMM2 (+b2): out = A @ g_t2 + b2 ---------------------------
__global__ void spmm2_kernel(const float* __restrict__ b2, float* __restrict__ out) {
    int w = (blockIdx.x * blockDim.x + threadIdx.x) >> 5;
    int lane = threadIdx.x & 31;
    if (w >= N_NODES) return;
    int s = g_rowptr[w], e = g_rowptr[w + 1];
    float acc = 0.f;
    for (int i = s; i < e; i++) {
        int   c = g_ecol[i];
        float v = g_eval[i];
        if (lane < N_CLASS) acc += v * __ldg(g_t2 + (size_t)c * N_CLASS + lane);
    }
    if (lane < N_CLASS) out[(size_t)w * N_CLASS + lane] = acc + b2[lane];
}

// ---------------- launch -----------------------------------------------------
extern "C" void kernel_launch(void* const* d_in, const int* in_sizes, int n_in,
                              void* d_out, int out_size) {
    const int*   x    = (const int*)d_in[0];
    const int*   rows = (const int*)d_in[1];
    const int*   cols = (const int*)d_in[2];
    const float* vals = (const float*)d_in[3];
    const float* emb  = (const float*)d_in[4];
    const float* W1   = (const float*)d_in[5];
    const float* b1   = (const float*)d_in[6];
    const float* W2   = (const float*)d_in[7];
    const float* b2   = (const float*)d_in[8];
    float* out = (float*)d_out;
    int E = in_sizes[1];

    cudaFuncSetAttribute(gemm1_mma_kernel,
                         cudaFuncAttributeMaxDynamicSharedMemorySize, GEMM_SMEM);

    detect_kernel<<<1, 256>>>(x, 512);
    embed_kernel<<<N_NODES, 256>>>(x, emb);
    convw1_kernel<<<(N_HID * IN_CH / 2 + 255) / 256, 256>>>(W1);
    gemm1_mma_kernel<<<dim3(N_HID / 128, M_PAD / 128), 256, GEMM_SMEM>>>();

    zero_counts_kernel<<<(N_NODES + 255) / 256, 256>>>();
    hist_kernel<<<(E + 255) / 256, 256>>>(rows, E);
    scan_kernel<<<1, 1024>>>();
    cursor_kernel<<<(N_NODES + 255) / 256, 256>>>();
    scatter_kernel<<<(E + 255) / 256, 256>>>(rows, cols, vals, E);

    spmm1_kernel<<<N_NODES, 128>>>(b1);
    gemm2_kernel<<<(N_NODES + 15) / 16, 256>>>(W2);
    spmm2_kernel<<<(N_NODES * 32 + 255) / 256, 256>>>(b2, out);
}

// round 6
// speedup vs baseline: 2.1500x; 1.0185x over previous
#include <cuda_runtime.h>
#include <cuda_bf16.h>
#include <cstdint>

#define N_NODES 15279
#define M_PAD   15360
#define E_EDGES 488928
#define IN_CH   1024
#define N_HID   512
#define N_CLASS 16
#define EMB_DIM 128

// ---------------- scratch (static device memory; no allocations) -------------
__device__ __nv_bfloat16 g_ahi[(size_t)M_PAD * IN_CH];   // 31.5 MB (pad rows stay 0)
__device__ __nv_bfloat16 g_alo[(size_t)M_PAD * IN_CH];   // 31.5 MB
__device__ __nv_bfloat16 g_bhi[(size_t)N_HID * IN_CH];   // 1 MB  (W1^T hi)
__device__ __nv_bfloat16 g_blo[(size_t)N_HID * IN_CH];   // 1 MB  (W1^T lo)
__device__ float g_t1[(size_t)N_NODES * N_HID];          // 31.3 MB h0@W1
__device__ float g_h1[(size_t)N_NODES * N_HID];          // 31.3 MB relu(spmm+b1)
__device__ float g_t2[(size_t)N_NODES * N_CLASS];        //  1.0 MB h1@W2
__device__ int   g_counts[N_NODES];
__device__ int   g_rowptr[N_NODES + 1];
__device__ int   g_cursor[N_NODES];
__device__ int   g_ecol[E_EDGES];
__device__ float g_eval[E_EDGES];
__device__ int   g_x64flag;

// ---------------- PTX helpers (sm_80+ features only) -------------------------
static __device__ __forceinline__ uint32_t s2u(const void* p) {
    uint32_t a;
    asm("{ .reg .u64 t; cvta.to.shared.u64 t, %1; cvt.u32.u64 %0, t; }" : "=r"(a) : "l"(p));
    return a;
}
static __device__ __forceinline__ void cp16(uint32_t dst, const void* src) {
    asm volatile("cp.async.cg.shared.global [%0], [%1], 16;" :: "r"(dst), "l"(src));
}
static __device__ __forceinline__ void cp_commit() {
    asm volatile("cp.async.commit_group;" ::: "memory");
}
static __device__ __forceinline__ void cp_wait3() {
    asm volatile("cp.async.wait_group 3;" ::: "memory");
}
static __device__ __forceinline__ void ldsm4(uint32_t* r, uint32_t a) {
    asm volatile("ldmatrix.sync.aligned.m8n8.x4.shared.b16 {%0,%1,%2,%3}, [%4];"
                 : "=r"(r[0]), "=r"(r[1]), "=r"(r[2]), "=r"(r[3]) : "r"(a));
}
static __device__ __forceinline__ void mma16816(float* d, const uint32_t* a, const uint32_t* b) {
    asm volatile(
        "mma.sync.aligned.m16n8k16.row.col.f32.bf16.bf16.f32 "
        "{%0,%1,%2,%3}, {%4,%5,%6,%7}, {%8,%9}, {%0,%1,%2,%3};"
        : "+f"(d[0]), "+f"(d[1]), "+f"(d[2]), "+f"(d[3])
        : "r"(a[0]), "r"(a[1]), "r"(a[2]), "r"(a[3]), "r"(b[0]), "r"(b[1]));
}

// ---------------- dtype detection for x (int32 vs int64) ---------------------
__global__ void detect_kernel(const int* x32, int n_pairs) {
    __shared__ int any;
    if (threadIdx.x == 0) any = 0;
    __syncthreads();
    int local = 0;
    for (int i = threadIdx.x; i < n_pairs; i += blockDim.x)
        if (x32[2 * i + 1] != 0) local = 1;
    if (local) atomicOr(&any, 1);
    __syncthreads();
    if (threadIdx.x == 0) g_x64flag = (any == 0);
}

// ---------------- embedding lookup + relu -> bf16 hi/lo ----------------------
__global__ void embed_kernel(const int* x32, const float* __restrict__ emb) {
    int n = blockIdx.x;
    int w = threadIdx.x >> 5, lane = threadIdx.x & 31;
    int idx;
    if (g_x64flag) idx = x32[2 * (n * 8 + w)];
    else           idx = x32[n * 8 + w];
    float4 v = ((const float4*)(emb + (size_t)idx * EMB_DIM))[lane];
    float f[4] = {fmaxf(v.x, 0.f), fmaxf(v.y, 0.f), fmaxf(v.z, 0.f), fmaxf(v.w, 0.f)};
    __nv_bfloat16 hi[4], lo[4];
#pragma unroll
    for (int i = 0; i < 4; i++) {
        hi[i] = __float2bfloat16(f[i]);
        lo[i] = __float2bfloat16(f[i] - __bfloat162float(hi[i]));
    }
    size_t off = (size_t)n * IN_CH + w * EMB_DIM + lane * 4;
    *(uint2*)(g_ahi + off) = *(uint2*)hi;
    *(uint2*)(g_alo + off) = *(uint2*)lo;
}

// W1 [K=1024, N=512] fp32 -> B [N=512, K=1024] bf16 hi/lo (transposed)
__global__ void convw1_kernel(const float* __restrict__ W1) {
    int i = blockIdx.x * blockDim.x + threadIdx.x;
    if (i >= N_HID * IN_CH / 2) return;
    int n = i / (IN_CH / 2);
    int k2 = (i % (IN_CH / 2)) * 2;
    float v0 = __ldg(W1 + (size_t)k2 * N_HID + n);
    float v1 = __ldg(W1 + (size_t)(k2 + 1) * N_HID + n);
    __nv_bfloat16 h0 = __float2bfloat16(v0), h1 = __float2bfloat16(v1);
    __nv_bfloat16 l0 = __float2bfloat16(v0 - __bfloat162float(h0));
    __nv_bfloat16 l1 = __float2bfloat16(v1 - __bfloat162float(h1));
    __nv_bfloat16 ph[2] = {h0, h1}, pl[2] = {l0, l1};
    *(uint32_t*)(g_bhi + (size_t)n * IN_CH + k2) = *(uint32_t*)ph;
    *(uint32_t*)(g_blo + (size_t)n * IN_CH + k2) = *(uint32_t*)pl;
}

// ---------------- GEMM1 via mma.sync bf16 hi/lo: t1 = A @ B^T ----------------
// block tile 128x64, BK=32, 8 warps (4Mx2N), warp tile 32x32,
// SW64-swizzled smem rows (64B), 4-stage cp.async pipeline, 2 CTAs/SM.
#define BKC 32
#define AT  8192                       // 128 rows x 32 bf16 x 2B
#define BT  4096                       // 64 rows x 32 bf16 x 2B
#define SSIZE (2 * AT + 2 * BT)        // 24576: Ahi, Alo, Bhi, Blo
#define NSTAGE 4
#define GEMM_SMEM (NSTAGE * SSIZE)     // 98304

static __device__ __forceinline__ void gissue(uint32_t sb, int s, int k0,
                                              int bm, int bn, int tid) {
    if (k0 < IN_CH) {
        uint32_t stage = sb + s * SSIZE;
        // A hi/lo: 512 16B-units each (128 rows x 4 units)
#pragma unroll
        for (int l = 0; l < 2; l++) {
            int unit = tid + l * 256;
            int r = unit >> 2, u = unit & 3;
            uint32_t bo = (r << 6) | (u << 4);
            uint32_t sw = bo ^ ((bo >> 3) & 0x30);
            const size_t go = (size_t)(bm + r) * IN_CH + k0 + u * 8;
            cp16(stage + sw, g_ahi + go);
            cp16(stage + AT + sw, g_alo + go);
        }
        // B hi/lo: 256 16B-units each (64 rows x 4 units)
        {
            int r = tid >> 2, u = tid & 3;
            uint32_t bo = (r << 6) | (u << 4);
            uint32_t sw = bo ^ ((bo >> 3) & 0x30);
            const size_t go = (size_t)(bn + r) * IN_CH + k0 + u * 8;
            cp16(stage + 2 * AT + sw, g_bhi + go);
            cp16(stage + 2 * AT + BT + sw, g_blo + go);
        }
    }
    cp_commit();
}

__global__ void __launch_bounds__(256, 2) gemm1_mma_kernel() {
    extern __shared__ char smem[];
    uint32_t sb = s2u(smem);
    const int tid = threadIdx.x;
    const int wid = tid >> 5, lane = tid & 31;
    const int bm = blockIdx.y * 128, bn = blockIdx.x * 64;
    const int warp_m = (wid & 3) * 32;
    const int warp_n = (wid >> 2) * 32;

    float acc[2][4][4];
#pragma unroll
    for (int mi = 0; mi < 2; mi++)
#pragma unroll
        for (int nj = 0; nj < 4; nj++)
#pragma unroll
            for (int q = 0; q < 4; q++) acc[mi][nj][q] = 0.f;

    gissue(sb, 0, 0, bm, bn, tid);
    gissue(sb, 1, BKC, bm, bn, tid);
    gissue(sb, 2, 2 * BKC, bm, bn, tid);
    gissue(sb, 3, 3 * BKC, bm, bn, tid);

    const int NCHUNK = IN_CH / BKC;   // 32
    for (int c = 0; c < NCHUNK; c++) {
        cp_wait3();
        __syncthreads();
        uint32_t stage = sb + (c & 3) * SSIZE;
#pragma unroll
        for (int kk = 0; kk < 2; kk++) {
            // A fragments (hi/lo), 2 m-subtiles of 16
            uint32_t ahi[2][4], alo[2][4];
#pragma unroll
            for (int mi = 0; mi < 2; mi++) {
                int row = warp_m + mi * 16 + ((lane >> 3) & 1) * 8 + (lane & 7);
                int unit = kk * 2 + (lane >> 4);
                uint32_t bo = (row << 6) | (unit << 4);
                uint32_t sw = bo ^ ((bo >> 3) & 0x30);
                ldsm4(ahi[mi], stage + sw);
                ldsm4(alo[mi], stage + AT + sw);
            }
            // B fragments (hi/lo), 4 n8 chunks via 2 x4-ldmatrix
            uint32_t bhi[4][2], blo[4][2];
#pragma unroll
            for (int p = 0; p < 2; p++) {
                int row = warp_n + p * 16 + (lane >> 4) * 8 + (lane & 7);
                int unit = kk * 2 + ((lane >> 3) & 1);
                uint32_t bo = (row << 6) | (unit << 4);
                uint32_t sw = bo ^ ((bo >> 3) & 0x30);
                uint32_t t[4];
                ldsm4(t, stage + 2 * AT + sw);
                bhi[2 * p][0] = t[0]; bhi[2 * p][1] = t[1];
                bhi[2 * p + 1][0] = t[2]; bhi[2 * p + 1][1] = t[3];
                ldsm4(t, stage + 2 * AT + BT + sw);
                blo[2 * p][0] = t[0]; blo[2 * p][1] = t[1];
                blo[2 * p + 1][0] = t[2]; blo[2 * p + 1][1] = t[3];
            }
#pragma unroll
            for (int mi = 0; mi < 2; mi++)
#pragma unroll
                for (int nj = 0; nj < 4; nj++) {
                    mma16816(acc[mi][nj], ahi[mi], bhi[nj]);
                    mma16816(acc[mi][nj], ahi[mi], blo[nj]);
                    mma16816(acc[mi][nj], alo[mi], bhi[nj]);
                }
        }
        __syncthreads();
        gissue(sb, c & 3, (c + NSTAGE) * BKC, bm, bn, tid);
    }

    // epilogue: c-frag rows l/4 and l/4+8, cols 2*(l%4)
#pragma unroll
    for (int mi = 0; mi < 2; mi++) {
        int r0 = bm + warp_m + mi * 16 + (lane >> 2);
        int r1 = r0 + 8;
#pragma unroll
        for (int nj = 0; nj < 4; nj++) {
            int col = bn + warp_n + nj * 8 + (lane & 3) * 2;
            if (r0 < N_NODES)
                *(float2*)(g_t1 + (size_t)r0 * N_HID + col) = make_float2(acc[mi][nj][0], acc[mi][nj][1]);
            if (r1 < N_NODES)
                *(float2*)(g_t1 + (size_t)r1 * N_HID + col) = make_float2(acc[mi][nj][2], acc[mi][nj][3]);
        }
    }
}

// ---------------- CSR build --------------------------------------------------
__global__ void zero_counts_kernel() {
    int i = blockIdx.x * blockDim.x + threadIdx.x;
    if (i < N_NODES) g_counts[i] = 0;
}
__global__ void hist_kernel(const int* __restrict__ rows, int E) {
    int i = blockIdx.x * blockDim.x + threadIdx.x;
    if (i < E) atomicAdd(&g_counts[rows[i]], 1);
}
__global__ void scan_kernel() {
    __shared__ int s[1024];
    int tid = threadIdx.x;
    int carry = 0;
    if (tid == 0) g_rowptr[0] = 0;
    for (int base = 0; base < N_NODES; base += 1024) {
        int v = (base + tid < N_NODES) ? g_counts[base + tid] : 0;
        s[tid] = v;
        __syncthreads();
        for (int off = 1; off < 1024; off <<= 1) {
            int t = (tid >= off) ? s[tid - off] : 0;
            __syncthreads();
            s[tid] += t;
            __syncthreads();
        }
        if (base + tid < N_NODES) g_rowptr[base + tid + 1] = carry + s[tid];
        carry += s[1023];
        __syncthreads();
    }
}
__global__ void cursor_kernel() {
    int i = blockIdx.x * blockDim.x + threadIdx.x;
    if (i < N_NODES) g_cursor[i] = g_rowptr[i];
}
__global__ void scatter_kernel(const int* __restrict__ rows, const int* __restrict__ cols,
                               const float* __restrict__ vals, int E) {
    int i = blockIdx.x * blockDim.x + threadIdx.x;
    if (i < E) {
        int r = rows[i];
        int p = atomicAdd(&g_cursor[r], 1);
        g_ecol[p] = cols[i];
        g_eval[p] = vals[i];
    }
}

// ---------------- SpMM1 (+b1, relu): g_h1 = relu(A @ g_t1 + b1) --------------
// one block of 128 threads per row; 2-way unrolled dual accumulators for MLP
__global__ __launch_bounds__(128) void spmm1_kernel(const float* __restrict__ b1) {
    int r = blockIdx.x;
    int tid = threadIdx.x;
    int s = g_rowptr[r], e = g_rowptr[r + 1];
    float4 acc0 = make_float4(0.f, 0.f, 0.f, 0.f);
    float4 acc1 = make_float4(0.f, 0.f, 0.f, 0.f);
    int i = s;
    for (; i + 1 < e; i += 2) {
        int   c0 = g_ecol[i],     c1 = g_ecol[i + 1];
        float v0 = g_eval[i],     v1 = g_eval[i + 1];
        float4 t0 = __ldg((const float4*)(g_t1 + (size_t)c0 * N_HID) + tid);
        float4 t1 = __ldg((const float4*)(g_t1 + (size_t)c1 * N_HID) + tid);
        acc0.x += v0 * t0.x; acc0.y += v0 * t0.y; acc0.z += v0 * t0.z; acc0.w += v0 * t0.w;
        acc1.x += v1 * t1.x; acc1.y += v1 * t1.y; acc1.z += v1 * t1.z; acc1.w += v1 * t1.w;
    }
    if (i < e) {
        int   c = g_ecol[i];
        float v = g_eval[i];
        float4 t = __ldg((const float4*)(g_t1 + (size_t)c * N_HID) + tid);
        acc0.x += v * t.x; acc0.y += v * t.y; acc0.z += v * t.z; acc0.w += v * t.w;
    }
    float4 bb = ((const float4*)b1)[tid];
    acc0.x = fmaxf(acc0.x + acc1.x + bb.x, 0.f);
    acc0.y = fmaxf(acc0.y + acc1.y + bb.y, 0.f);
    acc0.z = fmaxf(acc0.z + acc1.z + bb.z, 0.f);
    acc0.w = fmaxf(acc0.w + acc1.w + bb.w, 0.f);
    ((float4*)(g_h1 + (size_t)r * N_HID))[tid] = acc0;
}

// ---------------- GEMM2: g_t2 = g_h1[M,512] @ W2[512,16] ---------------------
__global__ __launch_bounds__(256) void gemm2_kernel(const float* __restrict__ W2) {
    __shared__ float Ws[N_HID * N_CLASS];
    for (int i = threadIdx.x; i < N_HID * N_CLASS; i += blockDim.x) Ws[i] = W2[i];
    __syncthreads();
    int row = blockIdx.x * 16 + (threadIdx.x >> 4);
    int c = threadIdx.x & 15;
    if (row >= N_NODES) return;
    const float4* a4 = (const float4*)(g_h1 + (size_t)row * N_HID);
    float acc = 0.f;
#pragma unroll 4
    for (int k = 0; k < N_HID / 4; k++) {
        float4 a = a4[k];
        acc += a.x * Ws[(4 * k + 0) * N_CLASS + c];
        acc += a.y * Ws[(4 * k + 1) * N_CLASS + c];
        acc += a.z * Ws[(4 * k + 2) * N_CLASS + c];
        acc += a.w * Ws[(4 * k + 3) * N_CLASS + c];
    }
    g_t2[(size_t)row * N_CLASS + c] = acc;
}

// ---------------- SpMM2 (+b2): out = A @ g_t2 + b2 ---------------------------
__global__ void spmm2_kernel(const float* __restrict__ b2, float* __restrict__ out) {
    int w = (blockIdx.x * blockDim.x + threadIdx.x) >> 5;
    int lane = threadIdx.x & 31;
    if (w >= N_NODES) return;
    int s = g_rowptr[w], e = g_rowptr[w + 1];
    float acc = 0.f;
    for (int i = s; i < e; i++) {
        int   c = g_ecol[i];
        float v = g_eval[i];
        if (lane < N_CLASS) acc += v * __ldg(g_t2 + (size_t)c * N_CLASS + lane);
    }
    if (lane < N_CLASS) out[(size_t)w * N_CLASS + lane] = acc + b2[lane];
}

// ---------------- launch -----------------------------------------------------
extern "C" void kernel_launch(void* const* d_in, const int* in_sizes, int n_in,
                              void* d_out, int out_size) {
    const int*   x    = (const int*)d_in[0];
    const int*   rows = (const int*)d_in[1];
    const int*   cols = (const int*)d_in[2];
    const float* vals = (const float*)d_in[3];
    const float* emb  = (const float*)d_in[4];
    const float* W1   = (const float*)d_in[5];
    const float* b1   = (const float*)d_in[6];
    const float* W2   = (const float*)d_in[7];
    const float* b2   = (const float*)d_in[8];
    float* out = (float*)d_out;
    int E = in_sizes[1];

    cudaFuncSetAttribute(gemm1_mma_kernel,
                         cudaFuncAttributeMaxDynamicSharedMemorySize, GEMM_SMEM);

    detect_kernel<<<1, 256>>>(x, 512);
    embed_kernel<<<N_NODES, 256>>>(x, emb);
    convw1_kernel<<<(N_HID * IN_CH / 2 + 255) / 256, 256>>>(W1);
    gemm1_mma_kernel<<<dim3(N_HID / 64, M_PAD / 128), 256, GEMM_SMEM>>>();

    zero_counts_kernel<<<(N_NODES + 255) / 256, 256>>>();
    hist_kernel<<<(E + 255) / 256, 256>>>(rows, E);
    scan_kernel<<<1, 1024>>>();
    cursor_kernel<<<(N_NODES + 255) / 256, 256>>>();
    scatter_kernel<<<(E + 255) / 256, 256>>>(rows, cols, vals, E);

    spmm1_kernel<<<N_NODES, 128>>>(b1);
    gemm2_kernel<<<(N_NODES + 15) / 16, 256>>>(W2);
    spmm2_kernel<<<(N_NODES * 32 + 255) / 256, 256>>>(b2, out);
}

// round 7
// speedup vs baseline: 2.5098x; 1.1674x over previous
#include <cuda_runtime.h>
#include <cuda_fp16.h>
#include <cstdint>

#define N_NODES 15279
#define M_PAD   15360
#define E_EDGES 488928
#define IN_CH   1024
#define N_HID   512
#define N_CLASS 16
#define EMB_DIM 128

// ---------------- scratch (static device memory; no allocations) -------------
__device__ __half g_a[(size_t)M_PAD * IN_CH];            // 31.5 MB fp16 activations (pad rows stay 0)
__device__ __half g_bhi[(size_t)N_HID * IN_CH];          // 1 MB  (W1^T hi fp16)
__device__ __half g_blo[(size_t)N_HID * IN_CH];          // 1 MB  (W1^T lo fp16)
__device__ float g_t1[(size_t)N_NODES * N_HID];          // 31.3 MB h0@W1
__device__ float g_h1[(size_t)N_NODES * N_HID];          // 31.3 MB relu(spmm+b1)
__device__ float g_t2[(size_t)N_NODES * N_CLASS];        //  1.0 MB h1@W2
__device__ int   g_counts[N_NODES];
__device__ int   g_rowptr[N_NODES + 1];
__device__ int   g_cursor[N_NODES];
__device__ int   g_ecol[E_EDGES];
__device__ float g_eval[E_EDGES];
__device__ int   g_x64flag;

// ---------------- PTX helpers (sm_80+ features only) -------------------------
static __device__ __forceinline__ uint32_t s2u(const void* p) {
    uint32_t a;
    asm("{ .reg .u64 t; cvta.to.shared.u64 t, %1; cvt.u32.u64 %0, t; }" : "=r"(a) : "l"(p));
    return a;
}
static __device__ __forceinline__ void cp16(uint32_t dst, const void* src) {
    asm volatile("cp.async.cg.shared.global [%0], [%1], 16;" :: "r"(dst), "l"(src));
}
static __device__ __forceinline__ void cp_commit() {
    asm volatile("cp.async.commit_group;" ::: "memory");
}
static __device__ __forceinline__ void cp_wait3() {
    asm volatile("cp.async.wait_group 3;" ::: "memory");
}
static __device__ __forceinline__ void ldsm4(uint32_t* r, uint32_t a) {
    asm volatile("ldmatrix.sync.aligned.m8n8.x4.shared.b16 {%0,%1,%2,%3}, [%4];"
                 : "=r"(r[0]), "=r"(r[1]), "=r"(r[2]), "=r"(r[3]) : "r"(a));
}
static __device__ __forceinline__ void mma16816f16(float* d, const uint32_t* a, const uint32_t* b) {
    asm volatile(
        "mma.sync.aligned.m16n8k16.row.col.f32.f16.f16.f32 "
        "{%0,%1,%2,%3}, {%4,%5,%6,%7}, {%8,%9}, {%0,%1,%2,%3};"
        : "+f"(d[0]), "+f"(d[1]), "+f"(d[2]), "+f"(d[3])
        : "r"(a[0]), "r"(a[1]), "r"(a[2]), "r"(a[3]), "r"(b[0]), "r"(b[1]));
}

// ---------------- dtype detection for x (int32 vs int64) ---------------------
__global__ void detect_kernel(const int* x32, int n_pairs) {
    __shared__ int any;
    if (threadIdx.x == 0) any = 0;
    __syncthreads();
    int local = 0;
    for (int i = threadIdx.x; i < n_pairs; i += blockDim.x)
        if (x32[2 * i + 1] != 0) local = 1;
    if (local) atomicOr(&any, 1);
    __syncthreads();
    if (threadIdx.x == 0) g_x64flag = (any == 0);
}

// ---------------- embedding lookup + relu -> fp16 ----------------------------
__global__ void embed_kernel(const int* x32, const float* __restrict__ emb) {
    int n = blockIdx.x;
    int w = threadIdx.x >> 5, lane = threadIdx.x & 31;
    int idx;
    if (g_x64flag) idx = x32[2 * (n * 8 + w)];
    else           idx = x32[n * 8 + w];
    float4 v = ((const float4*)(emb + (size_t)idx * EMB_DIM))[lane];
    __half h[4];
    h[0] = __float2half(fmaxf(v.x, 0.f));
    h[1] = __float2half(fmaxf(v.y, 0.f));
    h[2] = __float2half(fmaxf(v.z, 0.f));
    h[3] = __float2half(fmaxf(v.w, 0.f));
    size_t off = (size_t)n * IN_CH + w * EMB_DIM + lane * 4;
    *(uint2*)(g_a + off) = *(uint2*)h;
}

// W1 [K=1024, N=512] fp32 -> B [N=512, K=1024] fp16 hi/lo (transposed)
__global__ void convw1_kernel(const float* __restrict__ W1) {
    int i = blockIdx.x * blockDim.x + threadIdx.x;
    if (i >= N_HID * IN_CH / 2) return;
    int n = i / (IN_CH / 2);
    int k2 = (i % (IN_CH / 2)) * 2;
    float v0 = __ldg(W1 + (size_t)k2 * N_HID + n);
    float v1 = __ldg(W1 + (size_t)(k2 + 1) * N_HID + n);
    __half h0 = __float2half(v0), h1 = __float2half(v1);
    __half l0 = __float2half(v0 - __half2float(h0));
    __half l1 = __float2half(v1 - __half2float(h1));
    __half ph[2] = {h0, h1}, pl[2] = {l0, l1};
    *(uint32_t*)(g_bhi + (size_t)n * IN_CH + k2) = *(uint32_t*)ph;
    *(uint32_t*)(g_blo + (size_t)n * IN_CH + k2) = *(uint32_t*)pl;
}

// ---------------- GEMM1 via mma.sync fp16: t1 = A @ (Bhi+Blo)^T --------------
// block tile 128x64, BK=32, 8 warps (4Mx2N), warp tile 32x32,
// SW64-swizzled smem rows (64B), 4-stage cp.async pipeline, 2 CTAs/SM.
#define BKC 32
#define AT  8192                       // 128 rows x 32 fp16 x 2B
#define BT  4096                       // 64 rows x 32 fp16 x 2B
#define SSIZE (AT + 2 * BT)            // 16384: A, Bhi, Blo
#define NSTAGE 4
#define GEMM_SMEM (NSTAGE * SSIZE)     // 65536

static __device__ __forceinline__ void gissue(uint32_t sb, int s, int k0,
                                              int bm, int bn, int tid) {
    if (k0 < IN_CH) {
        uint32_t stage = sb + s * SSIZE;
        // A: 512 16B-units (128 rows x 4 units), 2 per thread
#pragma unroll
        for (int l = 0; l < 2; l++) {
            int unit = tid + l * 256;
            int r = unit >> 2, u = unit & 3;
            uint32_t bo = (r << 6) | (u << 4);
            uint32_t sw = bo ^ ((bo >> 3) & 0x30);
            cp16(stage + sw, g_a + (size_t)(bm + r) * IN_CH + k0 + u * 8);
        }
        // B hi/lo: 256 16B-units each (64 rows x 4 units), 1 per thread
        {
            int r = tid >> 2, u = tid & 3;
            uint32_t bo = (r << 6) | (u << 4);
            uint32_t sw = bo ^ ((bo >> 3) & 0x30);
            const size_t go = (size_t)(bn + r) * IN_CH + k0 + u * 8;
            cp16(stage + AT + sw, g_bhi + go);
            cp16(stage + AT + BT + sw, g_blo + go);
        }
    }
    cp_commit();
}

__global__ void __launch_bounds__(256, 2) gemm1_mma_kernel() {
    extern __shared__ char smem[];
    uint32_t sb = s2u(smem);
    const int tid = threadIdx.x;
    const int wid = tid >> 5, lane = tid & 31;
    const int bm = blockIdx.y * 128, bn = blockIdx.x * 64;
    const int warp_m = (wid & 3) * 32;
    const int warp_n = (wid >> 2) * 32;

    float acc[2][4][4];
#pragma unroll
    for (int mi = 0; mi < 2; mi++)
#pragma unroll
        for (int nj = 0; nj < 4; nj++)
#pragma unroll
            for (int q = 0; q < 4; q++) acc[mi][nj][q] = 0.f;

    gissue(sb, 0, 0, bm, bn, tid);
    gissue(sb, 1, BKC, bm, bn, tid);
    gissue(sb, 2, 2 * BKC, bm, bn, tid);
    gissue(sb, 3, 3 * BKC, bm, bn, tid);

    const int NCHUNK = IN_CH / BKC;   // 32
    for (int c = 0; c < NCHUNK; c++) {
        cp_wait3();
        __syncthreads();
        uint32_t stage = sb + (c & 3) * SSIZE;
#pragma unroll
        for (int kk = 0; kk < 2; kk++) {
            // A fragments, 2 m-subtiles of 16
            uint32_t af[2][4];
#pragma unroll
            for (int mi = 0; mi < 2; mi++) {
                int row = warp_m + mi * 16 + ((lane >> 3) & 1) * 8 + (lane & 7);
                int unit = kk * 2 + (lane >> 4);
                uint32_t bo = (row << 6) | (unit << 4);
                uint32_t sw = bo ^ ((bo >> 3) & 0x30);
                ldsm4(af[mi], stage + sw);
            }
            // B fragments (hi/lo), 4 n8 chunks via 2 x4-ldmatrix each
            uint32_t bhi[4][2], blo[4][2];
#pragma unroll
            for (int p = 0; p < 2; p++) {
                int row = warp_n + p * 16 + (lane >> 4) * 8 + (lane & 7);
                int unit = kk * 2 + ((lane >> 3) & 1);
                uint32_t bo = (row << 6) | (unit << 4);
                uint32_t sw = bo ^ ((bo >> 3) & 0x30);
                uint32_t t[4];
                ldsm4(t, stage + AT + sw);
                bhi[2 * p][0] = t[0]; bhi[2 * p][1] = t[1];
                bhi[2 * p + 1][0] = t[2]; bhi[2 * p + 1][1] = t[3];
                ldsm4(t, stage + AT + BT + sw);
                blo[2 * p][0] = t[0]; blo[2 * p][1] = t[1];
                blo[2 * p + 1][0] = t[2]; blo[2 * p + 1][1] = t[3];
            }
#pragma unroll
            for (int mi = 0; mi < 2; mi++)
#pragma unroll
                for (int nj = 0; nj < 4; nj++) {
                    mma16816f16(acc[mi][nj], af[mi], bhi[nj]);
                    mma16816f16(acc[mi][nj], af[mi], blo[nj]);
                }
        }
        __syncthreads();
        gissue(sb, c & 3, (c + NSTAGE) * BKC, bm, bn, tid);
    }

    // epilogue: c-frag rows l/4 and l/4+8, cols 2*(l%4)
#pragma unroll
    for (int mi = 0; mi < 2; mi++) {
        int r0 = bm + warp_m + mi * 16 + (lane >> 2);
        int r1 = r0 + 8;
#pragma unroll
        for (int nj = 0; nj < 4; nj++) {
            int col = bn + warp_n + nj * 8 + (lane & 3) * 2;
            if (r0 < N_NODES)
                *(float2*)(g_t1 + (size_t)r0 * N_HID + col) = make_float2(acc[mi][nj][0], acc[mi][nj][1]);
            if (r1 < N_NODES)
                *(float2*)(g_t1 + (size_t)r1 * N_HID + col) = make_float2(acc[mi][nj][2], acc[mi][nj][3]);
        }
    }
}

// ---------------- CSR build --------------------------------------------------
__global__ void zero_counts_kernel() {
    int i = blockIdx.x * blockDim.x + threadIdx.x;
    if (i < N_NODES) g_counts[i] = 0;
}
__global__ void hist_kernel(const int* __restrict__ rows, int E) {
    int i = blockIdx.x * blockDim.x + threadIdx.x;
    if (i < E) atomicAdd(&g_counts[rows[i]], 1);
}
// single-block scan; also seeds g_cursor with the exclusive prefix
__global__ void scan_kernel() {
    __shared__ int s[1024];
    int tid = threadIdx.x;
    int carry = 0;
    if (tid == 0) g_rowptr[0] = 0;
    for (int base = 0; base < N_NODES; base += 1024) {
        int v = (base + tid < N_NODES) ? g_counts[base + tid] : 0;
        s[tid] = v;
        __syncthreads();
        for (int off = 1; off < 1024; off <<= 1) {
            int t = (tid >= off) ? s[tid - off] : 0;
            __syncthreads();
            s[tid] += t;
            __syncthreads();
        }
        if (base + tid < N_NODES) {
            int incl = carry + s[tid];
            g_rowptr[base + tid + 1] = incl;
            g_cursor[base + tid] = incl - v;   // exclusive prefix
        }
        carry += s[1023];
        __syncthreads();
    }
}
__global__ void scatter_kernel(const int* __restrict__ rows, const int* __restrict__ cols,
                               const float* __restrict__ vals, int E) {
    int i = blockIdx.x * blockDim.x + threadIdx.x;
    if (i < E) {
        int r = rows[i];
        int p = atomicAdd(&g_cursor[r], 1);
        g_ecol[p] = cols[i];
        g_eval[p] = vals[i];
    }
}

// ---------------- SpMM1 (+b1, relu): g_h1 = relu(A @ g_t1 + b1) --------------
__global__ __launch_bounds__(128) void spmm1_kernel(const float* __restrict__ b1) {
    int r = blockIdx.x;
    int tid = threadIdx.x;
    int s = g_rowptr[r], e = g_rowptr[r + 1];
    float4 acc0 = make_float4(0.f, 0.f, 0.f, 0.f);
    float4 acc1 = make_float4(0.f, 0.f, 0.f, 0.f);
    int i = s;
    for (; i + 1 < e; i += 2) {
        int   c0 = g_ecol[i],     c1 = g_ecol[i + 1];
        float v0 = g_eval[i],     v1 = g_eval[i + 1];
        float4 t0 = __ldg((const float4*)(g_t1 + (size_t)c0 * N_HID) + tid);
        float4 t1 = __ldg((const float4*)(g_t1 + (size_t)c1 * N_HID) + tid);
        acc0.x += v0 * t0.x; acc0.y += v0 * t0.y; acc0.z += v0 * t0.z; acc0.w += v0 * t0.w;
        acc1.x += v1 * t1.x; acc1.y += v1 * t1.y; acc1.z += v1 * t1.z; acc1.w += v1 * t1.w;
    }
    if (i < e) {
        int   c = g_ecol[i];
        float v = g_eval[i];
        float4 t = __ldg((const float4*)(g_t1 + (size_t)c * N_HID) + tid);
        acc0.x += v * t.x; acc0.y += v * t.y; acc0.z += v * t.z; acc0.w += v * t.w;
    }
    float4 bb = ((const float4*)b1)[tid];
    acc0.x = fmaxf(acc0.x + acc1.x + bb.x, 0.f);
    acc0.y = fmaxf(acc0.y + acc1.y + bb.y, 0.f);
    acc0.z = fmaxf(acc0.z + acc1.z + bb.z, 0.f);
    acc0.w = fmaxf(acc0.w + acc1.w + bb.w, 0.f);
    ((float4*)(g_h1 + (size_t)r * N_HID))[tid] = acc0;
}

// ---------------- GEMM2: g_t2 = g_h1[M,512] @ W2[512,16] ---------------------
__global__ __launch_bounds__(256) void gemm2_kernel(const float* __restrict__ W2) {
    __shared__ float Ws[N_HID * N_CLASS];
    for (int i = threadIdx.x; i < N_HID * N_CLASS; i += blockDim.x) Ws[i] = W2[i];
    __syncthreads();
    int row = blockIdx.x * 16 + (threadIdx.x >> 4);
    int c = threadIdx.x & 15;
    if (row >= N_NODES) return;
    const float4* a4 = (const float4*)(g_h1 + (size_t)row * N_HID);
    float acc = 0.f;
#pragma unroll 4
    for (int k = 0; k < N_HID / 4; k++) {
        float4 a = a4[k];
        acc += a.x * Ws[(4 * k + 0) * N_CLASS + c];
        acc += a.y * Ws[(4 * k + 1) * N_CLASS + c];
        acc += a.z * Ws[(4 * k + 2) * N_CLASS + c];
        acc += a.w * Ws[(4 * k + 3) * N_CLASS + c];
    }
    g_t2[(size_t)row * N_CLASS + c] = acc;
}

// ---------------- SpMM2 (+b2): out = A @ g_t2 + b2 ---------------------------
__global__ void spmm2_kernel(const float* __restrict__ b2, float* __restrict__ out) {
    int w = (blockIdx.x * blockDim.x + threadIdx.x) >> 5;
    int lane = threadIdx.x & 31;
    if (w >= N_NODES) return;
    int s = g_rowptr[w], e = g_rowptr[w + 1];
    float acc = 0.f;
    for (int i = s; i < e; i++) {
        int   c = g_ecol[i];
        float v = g_eval[i];
        if (lane < N_CLASS) acc += v * __ldg(g_t2 + (size_t)c * N_CLASS + lane);
    }
    if (lane < N_CLASS) out[(size_t)w * N_CLASS + lane] = acc + b2[lane];
}

// ---------------- launch -----------------------------------------------------
extern "C" void kernel_launch(void* const* d_in, const int* in_sizes, int n_in,
                              void* d_out, int out_size) {
    const int*   x    = (const int*)d_in[0];
    const int*   rows = (const int*)d_in[1];
    const int*   cols = (const int*)d_in[2];
    const float* vals = (const float*)d_in[3];
    const float* emb  = (const float*)d_in[4];
    const float* W1   = (const float*)d_in[5];
    const float* b1   = (const float*)d_in[6];
    const float* W2   = (const float*)d_in[7];
    const float* b2   = (const float*)d_in[8];
    float* out = (float*)d_out;
    int E = in_sizes[1];

    cudaFuncSetAttribute(gemm1_mma_kernel,
                         cudaFuncAttributeMaxDynamicSharedMemorySize, GEMM_SMEM);

    detect_kernel<<<1, 256>>>(x, 512);
    embed_kernel<<<N_NODES, 256>>>(x, emb);
    convw1_kernel<<<(N_HID * IN_CH / 2 + 255) / 256, 256>>>(W1);
    gemm1_mma_kernel<<<dim3(N_HID / 64, M_PAD / 128), 256, GEMM_SMEM>>>();

    zero_counts_kernel<<<(N_NODES + 255) / 256, 256>>>();
    hist_kernel<<<(E + 255) / 256, 256>>>(rows, E);
    scan_kernel<<<1, 1024>>>();
    scatter_kernel<<<(E + 255) / 256, 256>>>(rows, cols, vals, E);

    spmm1_kernel<<<N_NODES, 128>>>(b1);
    gemm2_kernel<<<(N_NODES + 15) / 16, 256>>>(W2);
    spmm2_kernel<<<(N_NODES * 32 + 255) / 256, 256>>>(b2, out);
}

// round 8
// speedup vs baseline: 2.6061x; 1.0384x over previous
#include <cuda_runtime.h>
#include <cuda_fp16.h>
#include <cstdint>

#define N_NODES 15279
#define M_PAD   15360
#define E_EDGES 488928
#define IN_CH   1024
#define N_HID   512
#define N_CLASS 16
#define EMB_DIM 128

// ---------------- scratch (static device memory; no allocations) -------------
__device__ __half g_a[(size_t)M_PAD * IN_CH];            // 31.5 MB fp16 activations (pad rows stay 0)
__device__ __half g_bhi[(size_t)N_HID * IN_CH];          // 1 MB  (W1^T hi fp16)
__device__ __half g_blo[(size_t)N_HID * IN_CH];          // 1 MB  (W1^T lo fp16)
__device__ __half g_t1[(size_t)N_NODES * N_HID];         // 15.7 MB h0@W1 (fp16)
__device__ float g_h1[(size_t)N_NODES * N_HID];          // 31.3 MB relu(spmm+b1)
__device__ float g_t2[(size_t)N_NODES * N_CLASS];        //  1.0 MB h1@W2
__device__ int   g_counts[N_NODES];                      // zero at load; re-zeroed by scan
__device__ int   g_rowptr[N_NODES + 1];
__device__ int   g_cursor[N_NODES];
__device__ int   g_ecol[E_EDGES];
__device__ float g_eval[E_EDGES];
__device__ int   g_x64flag;

// ---------------- PTX helpers (sm_80+ features only) -------------------------
static __device__ __forceinline__ uint32_t s2u(const void* p) {
    uint32_t a;
    asm("{ .reg .u64 t; cvta.to.shared.u64 t, %1; cvt.u32.u64 %0, t; }" : "=r"(a) : "l"(p));
    return a;
}
static __device__ __forceinline__ void cp16(uint32_t dst, const void* src) {
    asm volatile("cp.async.cg.shared.global [%0], [%1], 16;" :: "r"(dst), "l"(src));
}
static __device__ __forceinline__ void cp_commit() {
    asm volatile("cp.async.commit_group;" ::: "memory");
}
static __device__ __forceinline__ void cp_wait3() {
    asm volatile("cp.async.wait_group 3;" ::: "memory");
}
static __device__ __forceinline__ void ldsm4(uint32_t* r, uint32_t a) {
    asm volatile("ldmatrix.sync.aligned.m8n8.x4.shared.b16 {%0,%1,%2,%3}, [%4];"
                 : "=r"(r[0]), "=r"(r[1]), "=r"(r[2]), "=r"(r[3]) : "r"(a));
}
static __device__ __forceinline__ void mma16816f16(float* d, const uint32_t* a, const uint32_t* b) {
    asm volatile(
        "mma.sync.aligned.m16n8k16.row.col.f32.f16.f16.f32 "
        "{%0,%1,%2,%3}, {%4,%5,%6,%7}, {%8,%9}, {%0,%1,%2,%3};"
        : "+f"(d[0]), "+f"(d[1]), "+f"(d[2]), "+f"(d[3])
        : "r"(a[0]), "r"(a[1]), "r"(a[2]), "r"(a[3]), "r"(b[0]), "r"(b[1]));
}

// ---------------- dtype detection for x (int32 vs int64) ---------------------
__global__ void detect_kernel(const int* x32, int n_pairs) {
    __shared__ int any;
    if (threadIdx.x == 0) any = 0;
    __syncthreads();
    int local = 0;
    for (int i = threadIdx.x; i < n_pairs; i += blockDim.x)
        if (x32[2 * i + 1] != 0) local = 1;
    if (local) atomicOr(&any, 1);
    __syncthreads();
    if (threadIdx.x == 0) g_x64flag = (any == 0);
}

// ---------------- embedding lookup + relu -> fp16 ----------------------------
__global__ void embed_kernel(const int* x32, const float* __restrict__ emb) {
    int n = blockIdx.x;
    int w = threadIdx.x >> 5, lane = threadIdx.x & 31;
    int idx;
    if (g_x64flag) idx = x32[2 * (n * 8 + w)];
    else           idx = x32[n * 8 + w];
    float4 v = ((const float4*)(emb + (size_t)idx * EMB_DIM))[lane];
    __half h[4];
    h[0] = __float2half(fmaxf(v.x, 0.f));
    h[1] = __float2half(fmaxf(v.y, 0.f));
    h[2] = __float2half(fmaxf(v.z, 0.f));
    h[3] = __float2half(fmaxf(v.w, 0.f));
    size_t off = (size_t)n * IN_CH + w * EMB_DIM + lane * 4;
    *(uint2*)(g_a + off) = *(uint2*)h;
}

// W1 [K=1024, N=512] fp32 -> B [N=512, K=1024] fp16 hi/lo (transposed)
__global__ void convw1_kernel(const float* __restrict__ W1) {
    int i = blockIdx.x * blockDim.x + threadIdx.x;
    if (i >= N_HID * IN_CH / 2) return;
    int n = i / (IN_CH / 2);
    int k2 = (i % (IN_CH / 2)) * 2;
    float v0 = __ldg(W1 + (size_t)k2 * N_HID + n);
    float v1 = __ldg(W1 + (size_t)(k2 + 1) * N_HID + n);
    __half h0 = __float2half(v0), h1 = __float2half(v1);
    __half l0 = __float2half(v0 - __half2float(h0));
    __half l1 = __float2half(v1 - __half2float(h1));
    __half ph[2] = {h0, h1}, pl[2] = {l0, l1};
    *(uint32_t*)(g_bhi + (size_t)n * IN_CH + k2) = *(uint32_t*)ph;
    *(uint32_t*)(g_blo + (size_t)n * IN_CH + k2) = *(uint32_t*)pl;
}

// ---------------- GEMM1 via mma.sync fp16: t1 = A @ (Bhi+Blo)^T --------------
// block tile 128x64, BK=32, 8 warps (4Mx2N), warp tile 32x32,
// SW64-swizzled smem rows (64B), 4-stage cp.async pipeline, 2 CTAs/SM.
#define BKC 32
#define AT  8192                       // 128 rows x 32 fp16 x 2B
#define BT  4096                       // 64 rows x 32 fp16 x 2B
#define SSIZE (AT + 2 * BT)            // 16384: A, Bhi, Blo
#define NSTAGE 4
#define GEMM_SMEM (NSTAGE * SSIZE)     // 65536

static __device__ __forceinline__ void gissue(uint32_t sb, int s, int k0,
                                              int bm, int bn, int tid) {
    if (k0 < IN_CH) {
        uint32_t stage = sb + s * SSIZE;
#pragma unroll
        for (int l = 0; l < 2; l++) {
            int unit = tid + l * 256;
            int r = unit >> 2, u = unit & 3;
            uint32_t bo = (r << 6) | (u << 4);
            uint32_t sw = bo ^ ((bo >> 3) & 0x30);
            cp16(stage + sw, g_a + (size_t)(bm + r) * IN_CH + k0 + u * 8);
        }
        {
            int r = tid >> 2, u = tid & 3;
            uint32_t bo = (r << 6) | (u << 4);
            uint32_t sw = bo ^ ((bo >> 3) & 0x30);
            const size_t go = (size_t)(bn + r) * IN_CH + k0 + u * 8;
            cp16(stage + AT + sw, g_bhi + go);
            cp16(stage + AT + BT + sw, g_blo + go);
        }
    }
    cp_commit();
}

__global__ void __launch_bounds__(256, 2) gemm1_mma_kernel() {
    extern __shared__ char smem[];
    uint32_t sb = s2u(smem);
    const int tid = threadIdx.x;
    const int wid = tid >> 5, lane = tid & 31;
    const int bm = blockIdx.y * 128, bn = blockIdx.x * 64;
    const int warp_m = (wid & 3) * 32;
    const int warp_n = (wid >> 2) * 32;

    float acc[2][4][4];
#pragma unroll
    for (int mi = 0; mi < 2; mi++)
#pragma unroll
        for (int nj = 0; nj < 4; nj++)
#pragma unroll
            for (int q = 0; q < 4; q++) acc[mi][nj][q] = 0.f;

    gissue(sb, 0, 0, bm, bn, tid);
    gissue(sb, 1, BKC, bm, bn, tid);
    gissue(sb, 2, 2 * BKC, bm, bn, tid);
    gissue(sb, 3, 3 * BKC, bm, bn, tid);

    const int NCHUNK = IN_CH / BKC;   // 32
    for (int c = 0; c < NCHUNK; c++) {
        cp_wait3();
        __syncthreads();
        uint32_t stage = sb + (c & 3) * SSIZE;
#pragma unroll
        for (int kk = 0; kk < 2; kk++) {
            uint32_t af[2][4];
#pragma unroll
            for (int mi = 0; mi < 2; mi++) {
                int row = warp_m + mi * 16 + ((lane >> 3) & 1) * 8 + (lane & 7);
                int unit = kk * 2 + (lane >> 4);
                uint32_t bo = (row << 6) | (unit << 4);
                uint32_t sw = bo ^ ((bo >> 3) & 0x30);
                ldsm4(af[mi], stage + sw);
            }
            uint32_t bhi[4][2], blo[4][2];
#pragma unroll
            for (int p = 0; p < 2; p++) {
                int row = warp_n + p * 16 + (lane >> 4) * 8 + (lane & 7);
                int unit = kk * 2 + ((lane >> 3) & 1);
                uint32_t bo = (row << 6) | (unit << 4);
                uint32_t sw = bo ^ ((bo >> 3) & 0x30);
                uint32_t t[4];
                ldsm4(t, stage + AT + sw);
                bhi[2 * p][0] = t[0]; bhi[2 * p][1] = t[1];
                bhi[2 * p + 1][0] = t[2]; bhi[2 * p + 1][1] = t[3];
                ldsm4(t, stage + AT + BT + sw);
                blo[2 * p][0] = t[0]; blo[2 * p][1] = t[1];
                blo[2 * p + 1][0] = t[2]; blo[2 * p + 1][1] = t[3];
            }
#pragma unroll
            for (int mi = 0; mi < 2; mi++)
#pragma unroll
                for (int nj = 0; nj < 4; nj++) {
                    mma16816f16(acc[mi][nj], af[mi], bhi[nj]);
                    mma16816f16(acc[mi][nj], af[mi], blo[nj]);
                }
        }
        __syncthreads();
        gissue(sb, c & 3, (c + NSTAGE) * BKC, bm, bn, tid);
    }

    // epilogue -> fp16 t1
#pragma unroll
    for (int mi = 0; mi < 2; mi++) {
        int r0 = bm + warp_m + mi * 16 + (lane >> 2);
        int r1 = r0 + 8;
#pragma unroll
        for (int nj = 0; nj < 4; nj++) {
            int col = bn + warp_n + nj * 8 + (lane & 3) * 2;
            if (r0 < N_NODES)
                *(__half2*)(g_t1 + (size_t)r0 * N_HID + col) =
                    __floats2half2_rn(acc[mi][nj][0], acc[mi][nj][1]);
            if (r1 < N_NODES)
                *(__half2*)(g_t1 + (size_t)r1 * N_HID + col) =
                    __floats2half2_rn(acc[mi][nj][2], acc[mi][nj][3]);
        }
    }
}

// ---------------- CSR build --------------------------------------------------
__global__ void hist_kernel(const int* __restrict__ rows, int E) {
    int i = blockIdx.x * blockDim.x + threadIdx.x;
    if (i < E) atomicAdd(&g_counts[rows[i]], 1);
}

// thread-coarsened shuffle scan, 1 block x 1024 threads, 15 elems/thread.
// Also zeroes g_counts (so hist starts clean on the next replay) and seeds
// g_cursor with the exclusive prefix.
#define SCAN_PER 15
__global__ void __launch_bounds__(1024) scan_kernel() {
    __shared__ int wsum[32];
    int tid = threadIdx.x;
    int lane = tid & 31, w = tid >> 5;
    int base = tid * SCAN_PER;
    int c[SCAN_PER];
    int sum = 0;
#pragma unroll
    for (int i = 0; i < SCAN_PER; i++) {
        int g = base + i;
        c[i] = (g < N_NODES) ? g_counts[g] : 0;
        if (g < N_NODES) g_counts[g] = 0;
        sum += c[i];
    }
    // warp inclusive scan of per-thread sums
    int incl = sum;
#pragma unroll
    for (int off = 1; off < 32; off <<= 1) {
        int t = __shfl_up_sync(0xFFFFFFFFu, incl, off);
        if (lane >= off) incl += t;
    }
    if (lane == 31) wsum[w] = incl;
    __syncthreads();
    if (w == 0) {
        int v = wsum[lane];
#pragma unroll
        for (int off = 1; off < 32; off <<= 1) {
            int t = __shfl_up_sync(0xFFFFFFFFu, v, off);
            if (lane >= off) v += t;
        }
        wsum[lane] = v;
    }
    __syncthreads();
    int run = (w > 0 ? wsum[w - 1] : 0) + incl - sum;   // exclusive prefix
    if (tid == 0) g_rowptr[0] = 0;
#pragma unroll
    for (int i = 0; i < SCAN_PER; i++) {
        int g = base + i;
        if (g < N_NODES) {
            g_cursor[g] = run;
            run += c[i];
            g_rowptr[g + 1] = run;
        }
    }
}

__global__ void scatter_kernel(const int* __restrict__ rows, const int* __restrict__ cols,
                               const float* __restrict__ vals, int E) {
    int i = blockIdx.x * blockDim.x + threadIdx.x;
    if (i < E) {
        int r = rows[i];
        int p = atomicAdd(&g_cursor[r], 1);
        g_ecol[p] = cols[i];
        g_eval[p] = vals[i];
    }
}

// ---------------- SpMM1 (+b1, relu): g_h1 = relu(A @ t1_fp16 + b1) -----------
__global__ __launch_bounds__(128) void spmm1_kernel(const float* __restrict__ b1) {
    int r = blockIdx.x;
    int tid = threadIdx.x;
    int s = g_rowptr[r], e = g_rowptr[r + 1];
    float4 acc0 = make_float4(0.f, 0.f, 0.f, 0.f);
    float4 acc1 = make_float4(0.f, 0.f, 0.f, 0.f);
    int i = s;
    for (; i + 1 < e; i += 2) {
        int   c0 = g_ecol[i],     c1 = g_ecol[i + 1];
        float v0 = g_eval[i],     v1 = g_eval[i + 1];
        uint2 r0 = __ldg((const uint2*)(g_t1 + (size_t)c0 * N_HID) + tid);
        uint2 r1 = __ldg((const uint2*)(g_t1 + (size_t)c1 * N_HID) + tid);
        float2 p0 = __half22float2(*(__half2*)&r0.x), p1 = __half22float2(*(__half2*)&r0.y);
        float2 q0 = __half22float2(*(__half2*)&r1.x), q1 = __half22float2(*(__half2*)&r1.y);
        acc0.x += v0 * p0.x; acc0.y += v0 * p0.y; acc0.z += v0 * p1.x; acc0.w += v0 * p1.y;
        acc1.x += v1 * q0.x; acc1.y += v1 * q0.y; acc1.z += v1 * q1.x; acc1.w += v1 * q1.y;
    }
    if (i < e) {
        int   c = g_ecol[i];
        float v = g_eval[i];
        uint2 r0 = __ldg((const uint2*)(g_t1 + (size_t)c * N_HID) + tid);
        float2 p0 = __half22float2(*(__half2*)&r0.x), p1 = __half22float2(*(__half2*)&r0.y);
        acc0.x += v * p0.x; acc0.y += v * p0.y; acc0.z += v * p1.x; acc0.w += v * p1.y;
    }
    float4 bb = ((const float4*)b1)[tid];
    acc0.x = fmaxf(acc0.x + acc1.x + bb.x, 0.f);
    acc0.y = fmaxf(acc0.y + acc1.y + bb.y, 0.f);
    acc0.z = fmaxf(acc0.z + acc1.z + bb.z, 0.f);
    acc0.w = fmaxf(acc0.w + acc1.w + bb.w, 0.f);
    ((float4*)(g_h1 + (size_t)r * N_HID))[tid] = acc0;
}

// ---------------- GEMM2: g_t2 = g_h1[M,512] @ W2[512,16] ---------------------
__global__ __launch_bounds__(256) void gemm2_kernel(const float* __restrict__ W2) {
    __shared__ float Ws[N_HID * N_CLASS];
    for (int i = threadIdx.x; i < N_HID * N_CLASS; i += blockDim.x) Ws[i] = W2[i];
    __syncthreads();
    int row = blockIdx.x * 16 + (threadIdx.x >> 4);
    int c = threadIdx.x & 15;
    if (row >= N_NODES) return;
    const float4* a4 = (const float4*)(g_h1 + (size_t)row * N_HID);
    float acc = 0.f;
#pragma unroll 4
    for (int k = 0; k < N_HID / 4; k++) {
        float4 a = a4[k];
        acc += a.x * Ws[(4 * k + 0) * N_CLASS + c];
        acc += a.y * Ws[(4 * k + 1) * N_CLASS + c];
        acc += a.z * Ws[(4 * k + 2) * N_CLASS + c];
        acc += a.w * Ws[(4 * k + 3) * N_CLASS + c];
    }
    g_t2[(size_t)row * N_CLASS + c] = acc;
}

// ---------------- SpMM2 (+b2): out = A @ g_t2 + b2 ---------------------------
__global__ void spmm2_kernel(const float* __restrict__ b2, float* __restrict__ out) {
    int w = (blockIdx.x * blockDim.x + threadIdx.x) >> 5;
    int lane = threadIdx.x & 31;
    if (w >= N_NODES) return;
    int s = g_rowptr[w], e = g_rowptr[w + 1];
    float acc = 0.f;
    for (int i = s; i < e; i++) {
        int   c = g_ecol[i];
        float v = g_eval[i];
        if (lane < N_CLASS) acc += v * __ldg(g_t2 + (size_t)c * N_CLASS + lane);
    }
    if (lane < N_CLASS) out[(size_t)w * N_CLASS + lane] = acc + b2[lane];
}

// ---------------- launch -----------------------------------------------------
extern "C" void kernel_launch(void* const* d_in, const int* in_sizes, int n_in,
                              void* d_out, int out_size) {
    const int*   x    = (const int*)d_in[0];
    const int*   rows = (const int*)d_in[1];
    const int*   cols = (const int*)d_in[2];
    const float* vals = (const float*)d_in[3];
    const float* emb  = (const float*)d_in[4];
    const float* W1   = (const float*)d_in[5];
    const float* b1   = (const float*)d_in[6];
    const float* W2   = (const float*)d_in[7];
    const float* b2   = (const float*)d_in[8];
    float* out = (float*)d_out;
    int E = in_sizes[1];

    cudaFuncSetAttribute(gemm1_mma_kernel,
                         cudaFuncAttributeMaxDynamicSharedMemorySize, GEMM_SMEM);

    detect_kernel<<<1, 256>>>(x, 512);
    embed_kernel<<<N_NODES, 256>>>(x, emb);
    convw1_kernel<<<(N_HID * IN_CH / 2 + 255) / 256, 256>>>(W1);
    gemm1_mma_kernel<<<dim3(N_HID / 64, M_PAD / 128), 256, GEMM_SMEM>>>();

    hist_kernel<<<(E + 255) / 256, 256>>>(rows, E);
    scan_kernel<<<1, 1024>>>();
    scatter_kernel<<<(E + 255) / 256, 256>>>(rows, cols, vals, E);

    spmm1_kernel<<<N_NODES, 128>>>(b1);
    gemm2_kernel<<<(N_NODES + 15) / 16, 256>>>(W2);
    spmm2_kernel<<<(N_NODES * 32 + 255) / 256, 256>>>(b2, out);
}

// round 9
// speedup vs baseline: 3.1313x; 1.2015x over previous
#include <cuda_runtime.h>
#include <cuda_fp16.h>
#include <cstdint>

#define N_NODES 15279
#define M_PAD   15360
#define E_EDGES 488928
#define IN_CH   1024
#define N_HID   512
#define N_CLASS 16
#define EMB_DIM 128

// ---------------- scratch (static device memory; no allocations) -------------
__device__ __half g_a[(size_t)M_PAD * IN_CH];            // 31.5 MB fp16 activations (pad rows stay 0)
__device__ __half g_b[(size_t)N_HID * IN_CH];            // 1 MB  (W1^T fp16)
__device__ __half g_t1[(size_t)N_NODES * N_HID];         // 15.7 MB h0@W1 (fp16)
__device__ __half g_h1[(size_t)N_NODES * N_HID];         // 15.7 MB relu(spmm+b1) (fp16)
__device__ float g_t2[(size_t)N_NODES * N_CLASS];        //  1.0 MB h1@W2
__device__ int   g_counts[N_NODES];                      // zero at load; re-zeroed by scan
__device__ int   g_rowptr[N_NODES + 1];
__device__ int   g_cursor[N_NODES];
__device__ int   g_ecol[E_EDGES];
__device__ float g_eval[E_EDGES];
__device__ int   g_x64flag;

// ---------------- PTX helpers (sm_80+ features only) -------------------------
static __device__ __forceinline__ uint32_t s2u(const void* p) {
    uint32_t a;
    asm("{ .reg .u64 t; cvta.to.shared.u64 t, %1; cvt.u32.u64 %0, t; }" : "=r"(a) : "l"(p));
    return a;
}
static __device__ __forceinline__ void cp16(uint32_t dst, const void* src) {
    asm volatile("cp.async.cg.shared.global [%0], [%1], 16;" :: "r"(dst), "l"(src));
}
static __device__ __forceinline__ void cp_commit() {
    asm volatile("cp.async.commit_group;" ::: "memory");
}
static __device__ __forceinline__ void cp_wait3() {
    asm volatile("cp.async.wait_group 3;" ::: "memory");
}
static __device__ __forceinline__ void ldsm4(uint32_t* r, uint32_t a) {
    asm volatile("ldmatrix.sync.aligned.m8n8.x4.shared.b16 {%0,%1,%2,%3}, [%4];"
                 : "=r"(r[0]), "=r"(r[1]), "=r"(r[2]), "=r"(r[3]) : "r"(a));
}
static __device__ __forceinline__ void mma16816f16(float* d, const uint32_t* a, const uint32_t* b) {
    asm volatile(
        "mma.sync.aligned.m16n8k16.row.col.f32.f16.f16.f32 "
        "{%0,%1,%2,%3}, {%4,%5,%6,%7}, {%8,%9}, {%0,%1,%2,%3};"
        : "+f"(d[0]), "+f"(d[1]), "+f"(d[2]), "+f"(d[3])
        : "r"(a[0]), "r"(a[1]), "r"(a[2]), "r"(a[3]), "r"(b[0]), "r"(b[1]));
}

// ---------------- dtype detection for x (int32 vs int64) ---------------------
__global__ void detect_kernel(const int* x32, int n_pairs) {
    __shared__ int any;
    if (threadIdx.x == 0) any = 0;
    __syncthreads();
    int local = 0;
    for (int i = threadIdx.x; i < n_pairs; i += blockDim.x)
        if (x32[2 * i + 1] != 0) local = 1;
    if (local) atomicOr(&any, 1);
    __syncthreads();
    if (threadIdx.x == 0) g_x64flag = (any == 0);
}

// ---------------- embedding lookup + relu -> fp16 ----------------------------
__global__ void embed_kernel(const int* x32, const float* __restrict__ emb) {
    int n = blockIdx.x;
    int w = threadIdx.x >> 5, lane = threadIdx.x & 31;
    int idx;
    if (g_x64flag) idx = x32[2 * (n * 8 + w)];
    else           idx = x32[n * 8 + w];
    float4 v = ((const float4*)(emb + (size_t)idx * EMB_DIM))[lane];
    __half h[4];
    h[0] = __float2half(fmaxf(v.x, 0.f));
    h[1] = __float2half(fmaxf(v.y, 0.f));
    h[2] = __float2half(fmaxf(v.z, 0.f));
    h[3] = __float2half(fmaxf(v.w, 0.f));
    size_t off = (size_t)n * IN_CH + w * EMB_DIM + lane * 4;
    *(uint2*)(g_a + off) = *(uint2*)h;
}

// W1 [K=1024, N=512] fp32 -> B [N=512, K=1024] fp16 (transposed)
__global__ void convw1_kernel(const float* __restrict__ W1) {
    int i = blockIdx.x * blockDim.x + threadIdx.x;
    if (i >= N_HID * IN_CH / 2) return;
    int n = i / (IN_CH / 2);
    int k2 = (i % (IN_CH / 2)) * 2;
    float v0 = __ldg(W1 + (size_t)k2 * N_HID + n);
    float v1 = __ldg(W1 + (size_t)(k2 + 1) * N_HID + n);
    __half ph[2] = {__float2half(v0), __float2half(v1)};
    *(uint32_t*)(g_b + (size_t)n * IN_CH + k2) = *(uint32_t*)ph;
}

// ---------------- GEMM1 via mma.sync fp16: t1 = A @ B^T ----------------------
// block tile 128x64, BK=32, 8 warps (4Mx2N), warp tile 32x32,
// SW64-swizzled smem rows (64B), 4-stage cp.async pipeline, 2 CTAs/SM.
#define BKC 32
#define AT  8192                       // 128 rows x 32 fp16 x 2B
#define BT  4096                       // 64 rows x 32 fp16 x 2B
#define SSIZE (AT + BT)                // 12288: A, B
#define NSTAGE 4
#define GEMM_SMEM (NSTAGE * SSIZE)     // 49152

static __device__ __forceinline__ void gissue(uint32_t sb, int s, int k0,
                                              int bm, int bn, int tid) {
    if (k0 < IN_CH) {
        uint32_t stage = sb + s * SSIZE;
#pragma unroll
        for (int l = 0; l < 2; l++) {
            int unit = tid + l * 256;
            int r = unit >> 2, u = unit & 3;
            uint32_t bo = (r << 6) | (u << 4);
            uint32_t sw = bo ^ ((bo >> 3) & 0x30);
            cp16(stage + sw, g_a + (size_t)(bm + r) * IN_CH + k0 + u * 8);
        }
        {
            int r = tid >> 2, u = tid & 3;
            uint32_t bo = (r << 6) | (u << 4);
            uint32_t sw = bo ^ ((bo >> 3) & 0x30);
            cp16(stage + AT + sw, g_b + (size_t)(bn + r) * IN_CH + k0 + u * 8);
        }
    }
    cp_commit();
}

__global__ void __launch_bounds__(256, 2) gemm1_mma_kernel() {
    extern __shared__ char smem[];
    uint32_t sb = s2u(smem);
    const int tid = threadIdx.x;
    const int wid = tid >> 5, lane = tid & 31;
    const int bm = blockIdx.y * 128, bn = blockIdx.x * 64;
    const int warp_m = (wid & 3) * 32;
    const int warp_n = (wid >> 2) * 32;

    float acc[2][4][4];
#pragma unroll
    for (int mi = 0; mi < 2; mi++)
#pragma unroll
        for (int nj = 0; nj < 4; nj++)
#pragma unroll
            for (int q = 0; q < 4; q++) acc[mi][nj][q] = 0.f;

    gissue(sb, 0, 0, bm, bn, tid);
    gissue(sb, 1, BKC, bm, bn, tid);
    gissue(sb, 2, 2 * BKC, bm, bn, tid);
    gissue(sb, 3, 3 * BKC, bm, bn, tid);

    const int NCHUNK = IN_CH / BKC;   // 32
    for (int c = 0; c < NCHUNK; c++) {
        cp_wait3();
        __syncthreads();
        uint32_t stage = sb + (c & 3) * SSIZE;
#pragma unroll
        for (int kk = 0; kk < 2; kk++) {
            uint32_t af[2][4];
#pragma unroll
            for (int mi = 0; mi < 2; mi++) {
                int row = warp_m + mi * 16 + ((lane >> 3) & 1) * 8 + (lane & 7);
                int unit = kk * 2 + (lane >> 4);
                uint32_t bo = (row << 6) | (unit << 4);
                uint32_t sw = bo ^ ((bo >> 3) & 0x30);
                ldsm4(af[mi], stage + sw);
            }
            uint32_t bf[4][2];
#pragma unroll
            for (int p = 0; p < 2; p++) {
                int row = warp_n + p * 16 + (lane >> 4) * 8 + (lane & 7);
                int unit = kk * 2 + ((lane >> 3) & 1);
                uint32_t bo = (row << 6) | (unit << 4);
                uint32_t sw = bo ^ ((bo >> 3) & 0x30);
                uint32_t t[4];
                ldsm4(t, stage + AT + sw);
                bf[2 * p][0] = t[0]; bf[2 * p][1] = t[1];
                bf[2 * p + 1][0] = t[2]; bf[2 * p + 1][1] = t[3];
            }
#pragma unroll
            for (int mi = 0; mi < 2; mi++)
#pragma unroll
                for (int nj = 0; nj < 4; nj++)
                    mma16816f16(acc[mi][nj], af[mi], bf[nj]);
        }
        __syncthreads();
        gissue(sb, c & 3, (c + NSTAGE) * BKC, bm, bn, tid);
    }

    // epilogue -> fp16 t1
#pragma unroll
    for (int mi = 0; mi < 2; mi++) {
        int r0 = bm + warp_m + mi * 16 + (lane >> 2);
        int r1 = r0 + 8;
#pragma unroll
        for (int nj = 0; nj < 4; nj++) {
            int col = bn + warp_n + nj * 8 + (lane & 3) * 2;
            if (r0 < N_NODES)
                *(__half2*)(g_t1 + (size_t)r0 * N_HID + col) =
                    __floats2half2_rn(acc[mi][nj][0], acc[mi][nj][1]);
            if (r1 < N_NODES)
                *(__half2*)(g_t1 + (size_t)r1 * N_HID + col) =
                    __floats2half2_rn(acc[mi][nj][2], acc[mi][nj][3]);
        }
    }
}

// ---------------- CSR build --------------------------------------------------
__global__ void hist_kernel(const int* __restrict__ rows, int E) {
    int i = blockIdx.x * blockDim.x + threadIdx.x;
    if (i < E) atomicAdd(&g_counts[rows[i]], 1);
}

// thread-coarsened shuffle scan; zeroes g_counts and seeds g_cursor
#define SCAN_PER 15
__global__ void __launch_bounds__(1024) scan_kernel() {
    __shared__ int wsum[32];
    int tid = threadIdx.x;
    int lane = tid & 31, w = tid >> 5;
    int base = tid * SCAN_PER;
    int c[SCAN_PER];
    int sum = 0;
#pragma unroll
    for (int i = 0; i < SCAN_PER; i++) {
        int g = base + i;
        c[i] = (g < N_NODES) ? g_counts[g] : 0;
        if (g < N_NODES) g_counts[g] = 0;
        sum += c[i];
    }
    int incl = sum;
#pragma unroll
    for (int off = 1; off < 32; off <<= 1) {
        int t = __shfl_up_sync(0xFFFFFFFFu, incl, off);
        if (lane >= off) incl += t;
    }
    if (lane == 31) wsum[w] = incl;
    __syncthreads();
    if (w == 0) {
        int v = wsum[lane];
#pragma unroll
        for (int off = 1; off < 32; off <<= 1) {
            int t = __shfl_up_sync(0xFFFFFFFFu, v, off);
            if (lane >= off) v += t;
        }
        wsum[lane] = v;
    }
    __syncthreads();
    int run = (w > 0 ? wsum[w - 1] : 0) + incl - sum;   // exclusive prefix
    if (tid == 0) g_rowptr[0] = 0;
#pragma unroll
    for (int i = 0; i < SCAN_PER; i++) {
        int g = base + i;
        if (g < N_NODES) {
            g_cursor[g] = run;
            run += c[i];
            g_rowptr[g + 1] = run;
        }
    }
}

__global__ void scatter_kernel(const int* __restrict__ rows, const int* __restrict__ cols,
                               const float* __restrict__ vals, int E) {
    int i = blockIdx.x * blockDim.x + threadIdx.x;
    if (i < E) {
        int r = rows[i];
        int p = atomicAdd(&g_cursor[r], 1);
        g_ecol[p] = cols[i];
        g_eval[p] = vals[i];
    }
}

// ---------------- SpMM1 (+b1, relu): h1 = relu(A @ t1 + b1) -> fp16 ----------
__global__ __launch_bounds__(128) void spmm1_kernel(const float* __restrict__ b1) {
    int r = blockIdx.x;
    int tid = threadIdx.x;
    int s = g_rowptr[r], e = g_rowptr[r + 1];
    float4 acc0 = make_float4(0.f, 0.f, 0.f, 0.f);
    float4 acc1 = make_float4(0.f, 0.f, 0.f, 0.f);
    int i = s;
    for (; i + 1 < e; i += 2) {
        int   c0 = g_ecol[i],     c1 = g_ecol[i + 1];
        float v0 = g_eval[i],     v1 = g_eval[i + 1];
        uint2 r0 = __ldg((const uint2*)(g_t1 + (size_t)c0 * N_HID) + tid);
        uint2 r1 = __ldg((const uint2*)(g_t1 + (size_t)c1 * N_HID) + tid);
        float2 p0 = __half22float2(*(__half2*)&r0.x), p1 = __half22float2(*(__half2*)&r0.y);
        float2 q0 = __half22float2(*(__half2*)&r1.x), q1 = __half22float2(*(__half2*)&r1.y);
        acc0.x += v0 * p0.x; acc0.y += v0 * p0.y; acc0.z += v0 * p1.x; acc0.w += v0 * p1.y;
        acc1.x += v1 * q0.x; acc1.y += v1 * q0.y; acc1.z += v1 * q1.x; acc1.w += v1 * q1.y;
    }
    if (i < e) {
        int   c = g_ecol[i];
        float v = g_eval[i];
        uint2 r0 = __ldg((const uint2*)(g_t1 + (size_t)c * N_HID) + tid);
        float2 p0 = __half22float2(*(__half2*)&r0.x), p1 = __half22float2(*(__half2*)&r0.y);
        acc0.x += v * p0.x; acc0.y += v * p0.y; acc0.z += v * p1.x; acc0.w += v * p1.y;
    }
    float4 bb = ((const float4*)b1)[tid];
    float hx = fmaxf(acc0.x + acc1.x + bb.x, 0.f);
    float hy = fmaxf(acc0.y + acc1.y + bb.y, 0.f);
    float hz = fmaxf(acc0.z + acc1.z + bb.z, 0.f);
    float hw = fmaxf(acc0.w + acc1.w + bb.w, 0.f);
    uint2 o;
    *(__half2*)&o.x = __floats2half2_rn(hx, hy);
    *(__half2*)&o.y = __floats2half2_rn(hz, hw);
    ((uint2*)(g_h1 + (size_t)r * N_HID))[tid] = o;
}

// ---------------- GEMM2: g_t2 = h1_fp16[M,512] @ W2[512,16] ------------------
__global__ __launch_bounds__(256) void gemm2_kernel(const float* __restrict__ W2) {
    __shared__ float Ws[N_HID * N_CLASS];
    for (int i = threadIdx.x; i < N_HID * N_CLASS; i += blockDim.x) Ws[i] = W2[i];
    __syncthreads();
    int row = blockIdx.x * 16 + (threadIdx.x >> 4);
    int c = threadIdx.x & 15;
    if (row >= N_NODES) return;
    const uint2* a4 = (const uint2*)(g_h1 + (size_t)row * N_HID);
    float acc = 0.f;
#pragma unroll 4
    for (int k = 0; k < N_HID / 4; k++) {
        uint2 r = a4[k];
        float2 a0 = __half22float2(*(__half2*)&r.x);
        float2 a1 = __half22float2(*(__half2*)&r.y);
        acc += a0.x * Ws[(4 * k + 0) * N_CLASS + c];
        acc += a0.y * Ws[(4 * k + 1) * N_CLASS + c];
        acc += a1.x * Ws[(4 * k + 2) * N_CLASS + c];
        acc += a1.y * Ws[(4 * k + 3) * N_CLASS + c];
    }
    g_t2[(size_t)row * N_CLASS + c] = acc;
}

// ---------------- SpMM2 (+b2): out = A @ g_t2 + b2 ---------------------------
__global__ void spmm2_kernel(const float* __restrict__ b2, float* __restrict__ out) {
    int w = (blockIdx.x * blockDim.x + threadIdx.x) >> 5;
    int lane = threadIdx.x & 31;
    if (w >= N_NODES) return;
    int s = g_rowptr[w], e = g_rowptr[w + 1];
    float acc = 0.f;
    for (int i = s; i < e; i++) {
        int   c = g_ecol[i];
        float v = g_eval[i];
        if (lane < N_CLASS) acc += v * __ldg(g_t2 + (size_t)c * N_CLASS + lane);
    }
    if (lane < N_CLASS) out[(size_t)w * N_CLASS + lane] = acc + b2[lane];
}

// ---------------- launch -----------------------------------------------------
extern "C" void kernel_launch(void* const* d_in, const int* in_sizes, int n_in,
                              void* d_out, int out_size) {
    const int*   x    = (const int*)d_in[0];
    const int*   rows = (const int*)d_in[1];
    const int*   cols = (const int*)d_in[2];
    const float* vals = (const float*)d_in[3];
    const float* emb  = (const float*)d_in[4];
    const float* W1   = (const float*)d_in[5];
    const float* b1   = (const float*)d_in[6];
    const float* W2   = (const float*)d_in[7];
    const float* b2   = (const float*)d_in[8];
    float* out = (float*)d_out;
    int E = in_sizes[1];

    cudaFuncSetAttribute(gemm1_mma_kernel,
                         cudaFuncAttributeMaxDynamicSharedMemorySize, GEMM_SMEM);

    detect_kernel<<<1, 256>>>(x, 512);
    embed_kernel<<<N_NODES, 256>>>(x, emb);
    convw1_kernel<<<(N_HID * IN_CH / 2 + 255) / 256, 256>>>(W1);
    gemm1_mma_kernel<<<dim3(N_HID / 64, M_PAD / 128), 256, GEMM_SMEM>>>();

    hist_kernel<<<(E + 255) / 256, 256>>>(rows, E);
    scan_kernel<<<1, 1024>>>();
    scatter_kernel<<<(E + 255) / 256, 256>>>(rows, cols, vals, E);

    spmm1_kernel<<<N_NODES, 128>>>(b1);
    gemm2_kernel<<<(N_NODES + 15) / 16, 256>>>(W2);
    spmm2_kernel<<<(N_NODES * 32 + 255) / 256, 256>>>(b2, out);
}

// round 10
// speedup vs baseline: 3.1852x; 1.0172x over previous
#include <cuda_runtime.h>
#include <cuda_fp16.h>
#include <cstdint>

#define N_NODES 15279
#define M_PAD   15360
#define E_EDGES 488928
#define IN_CH   1024
#define N_HID   512
#define N_CLASS 16
#define EMB_DIM 128

// ---------------- scratch (static device memory; no allocations) -------------
__device__ __half g_a[(size_t)M_PAD * IN_CH];            // 31.5 MB fp16 activations (pad rows stay 0)
__device__ __half g_b[(size_t)N_HID * IN_CH];            // 1 MB  (W1^T fp16)
__device__ __half g_t1[(size_t)N_NODES * N_HID];         // 15.7 MB h0@W1 (fp16)
__device__ __half g_h1[(size_t)N_NODES * N_HID];         // 15.7 MB relu(spmm+b1) (fp16)
__device__ float g_t2[(size_t)N_NODES * N_CLASS];        //  1.0 MB h1@W2
__device__ int   g_counts[N_NODES];                      // zero at load; re-zeroed by scan
__device__ int   g_rowptr[N_NODES + 1];
__device__ int   g_cursor[N_NODES];
__device__ int   g_ecol[E_EDGES];
__device__ float g_eval[E_EDGES];
__device__ int   g_x64flag;

// ---------------- PTX helpers (sm_80+ features only) -------------------------
static __device__ __forceinline__ uint32_t s2u(const void* p) {
    uint32_t a;
    asm("{ .reg .u64 t; cvta.to.shared.u64 t, %1; cvt.u32.u64 %0, t; }" : "=r"(a) : "l"(p));
    return a;
}
static __device__ __forceinline__ void cp16(uint32_t dst, const void* src) {
    asm volatile("cp.async.cg.shared.global [%0], [%1], 16;" :: "r"(dst), "l"(src));
}
static __device__ __forceinline__ void cp_commit() {
    asm volatile("cp.async.commit_group;" ::: "memory");
}
static __device__ __forceinline__ void cp_wait3() {
    asm volatile("cp.async.wait_group 3;" ::: "memory");
}
static __device__ __forceinline__ void ldsm4(uint32_t* r, uint32_t a) {
    asm volatile("ldmatrix.sync.aligned.m8n8.x4.shared.b16 {%0,%1,%2,%3}, [%4];"
                 : "=r"(r[0]), "=r"(r[1]), "=r"(r[2]), "=r"(r[3]) : "r"(a));
}
static __device__ __forceinline__ void mma16816f16(float* d, const uint32_t* a, const uint32_t* b) {
    asm volatile(
        "mma.sync.aligned.m16n8k16.row.col.f32.f16.f16.f32 "
        "{%0,%1,%2,%3}, {%4,%5,%6,%7}, {%8,%9}, {%0,%1,%2,%3};"
        : "+f"(d[0]), "+f"(d[1]), "+f"(d[2]), "+f"(d[3])
        : "r"(a[0]), "r"(a[1]), "r"(a[2]), "r"(a[3]), "r"(b[0]), "r"(b[1]));
}

// ---------------- dtype detection for x (int32 vs int64) ---------------------
__global__ void detect_kernel(const int* x32, int n_pairs) {
    __shared__ int any;
    if (threadIdx.x == 0) any = 0;
    __syncthreads();
    int local = 0;
    for (int i = threadIdx.x; i < n_pairs; i += blockDim.x)
        if (x32[2 * i + 1] != 0) local = 1;
    if (local) atomicOr(&any, 1);
    __syncthreads();
    if (threadIdx.x == 0) g_x64flag = (any == 0);
}

// ---------------- embedding lookup + relu -> fp16 ----------------------------
__global__ void embed_kernel(const int* x32, const float* __restrict__ emb) {
    int n = blockIdx.x;
    int w = threadIdx.x >> 5, lane = threadIdx.x & 31;
    int idx;
    if (g_x64flag) idx = x32[2 * (n * 8 + w)];
    else           idx = x32[n * 8 + w];
    float4 v = ((const float4*)(emb + (size_t)idx * EMB_DIM))[lane];
    __half h[4];
    h[0] = __float2half(fmaxf(v.x, 0.f));
    h[1] = __float2half(fmaxf(v.y, 0.f));
    h[2] = __float2half(fmaxf(v.z, 0.f));
    h[3] = __float2half(fmaxf(v.w, 0.f));
    size_t off = (size_t)n * IN_CH + w * EMB_DIM + lane * 4;
    *(uint2*)(g_a + off) = *(uint2*)h;
}

// W1 [K=1024, N=512] fp32 -> B [N=512, K=1024] fp16 (transposed)
__global__ void convw1_kernel(const float* __restrict__ W1) {
    int i = blockIdx.x * blockDim.x + threadIdx.x;
    if (i >= N_HID * IN_CH / 2) return;
    int n = i / (IN_CH / 2);
    int k2 = (i % (IN_CH / 2)) * 2;
    float v0 = __ldg(W1 + (size_t)k2 * N_HID + n);
    float v1 = __ldg(W1 + (size_t)(k2 + 1) * N_HID + n);
    __half ph[2] = {__float2half(v0), __float2half(v1)};
    *(uint32_t*)(g_b + (size_t)n * IN_CH + k2) = *(uint32_t*)ph;
}

// ---------------- GEMM1 via mma.sync fp16: t1 = A @ B^T ----------------------
// block tile 128x64, BK=64, 8 warps (4Mx2N), warp tile 32x32,
// SW128-swizzled smem rows (128B), 4-stage cp.async pipeline, 2 CTAs/SM,
// fragment double-buffering across the 4 kk-steps.
#define BKC 64
#define AT  16384                      // 128 rows x 64 fp16 x 2B
#define BT  8192                       // 64 rows x 64 fp16 x 2B
#define SSIZE (AT + BT)                // 24576
#define NSTAGE 4
#define GEMM_SMEM (NSTAGE * SSIZE)     // 98304

static __device__ __forceinline__ void gissue(uint32_t sb, int s, int k0,
                                              int bm, int bn, int tid) {
    if (k0 < IN_CH) {
        uint32_t stage = sb + s * SSIZE;
        // A: 1024 16B-units (128 rows x 8 units), 4 per thread
#pragma unroll
        for (int l = 0; l < 4; l++) {
            int unit = tid + l * 256;
            int r = unit >> 3, u = unit & 7;
            uint32_t bo = (r << 7) | (u << 4);
            uint32_t sw = bo ^ ((bo >> 3) & 0x70);
            cp16(stage + sw, g_a + (size_t)(bm + r) * IN_CH + k0 + u * 8);
        }
        // B: 512 16B-units (64 rows x 8 units), 2 per thread
#pragma unroll
        for (int l = 0; l < 2; l++) {
            int unit = tid + l * 256;
            int r = unit >> 3, u = unit & 7;
            uint32_t bo = (r << 7) | (u << 4);
            uint32_t sw = bo ^ ((bo >> 3) & 0x70);
            cp16(stage + AT + sw, g_b + (size_t)(bn + r) * IN_CH + k0 + u * 8);
        }
    }
    cp_commit();
}

__global__ void __launch_bounds__(256, 2) gemm1_mma_kernel() {
    extern __shared__ char smem[];
    uint32_t sb = s2u(smem);
    const int tid = threadIdx.x;
    const int wid = tid >> 5, lane = tid & 31;
    const int bm = blockIdx.y * 128, bn = blockIdx.x * 64;
    const int warp_m = (wid & 3) * 32;
    const int warp_n = (wid >> 2) * 32;

    // precomputed per-lane ldsm byte offsets (swizzled) for unit parity 0
    // A: row = warp_m + mi*16 + ((lane>>3)&1)*8 + (lane&7), unit base (lane>>4)
    // B: row = warp_n + p*16 + (lane>>4)*8 + (lane&7),  unit base ((lane>>3)&1)
    uint32_t a_off[2], b_off[2];
#pragma unroll
    for (int mi = 0; mi < 2; mi++) {
        int row = warp_m + mi * 16 + ((lane >> 3) & 1) * 8 + (lane & 7);
        a_off[mi] = (uint32_t)((row << 7) | ((lane >> 4) << 4));
    }
#pragma unroll
    for (int p = 0; p < 2; p++) {
        int row = warp_n + p * 16 + (lane >> 4) * 8 + (lane & 7);
        b_off[p] = (uint32_t)((row << 7) | (((lane >> 3) & 1) << 4));
    }

    float acc[2][4][4];
#pragma unroll
    for (int mi = 0; mi < 2; mi++)
#pragma unroll
        for (int nj = 0; nj < 4; nj++)
#pragma unroll
            for (int q = 0; q < 4; q++) acc[mi][nj][q] = 0.f;

    gissue(sb, 0, 0, bm, bn, tid);
    gissue(sb, 1, BKC, bm, bn, tid);
    gissue(sb, 2, 2 * BKC, bm, bn, tid);
    gissue(sb, 3, 3 * BKC, bm, bn, tid);

    uint32_t af[2][2][4];     // [buf][mi][4]
    uint32_t bf[2][4][2];     // [buf][nj][2]

    const int NCHUNK = IN_CH / BKC;   // 16
    for (int c = 0; c < NCHUNK; c++) {
        cp_wait3();
        __syncthreads();
        uint32_t stage = sb + (c & 3) * SSIZE;

        // load kk=0 fragments into buf 0
#pragma unroll
        for (int mi = 0; mi < 2; mi++) {
            uint32_t bo = a_off[mi];
            ldsm4(af[0][mi], stage + (bo ^ ((bo >> 3) & 0x70)));
        }
#pragma unroll
        for (int p = 0; p < 2; p++) {
            uint32_t bo = b_off[p];
            uint32_t t[4];
            ldsm4(t, stage + AT + (bo ^ ((bo >> 3) & 0x70)));
            bf[0][2 * p][0] = t[0]; bf[0][2 * p][1] = t[1];
            bf[0][2 * p + 1][0] = t[2]; bf[0][2 * p + 1][1] = t[3];
        }

#pragma unroll
        for (int kk = 0; kk < 4; kk++) {
            int cur = kk & 1, nxt = cur ^ 1;
            if (kk < 3) {
                uint32_t ubase = (uint32_t)((kk + 1) * 2) << 4;
#pragma unroll
                for (int mi = 0; mi < 2; mi++) {
                    uint32_t bo = a_off[mi] + ubase;
                    ldsm4(af[nxt][mi], stage + (bo ^ ((bo >> 3) & 0x70)));
                }
#pragma unroll
                for (int p = 0; p < 2; p++) {
                    uint32_t bo = b_off[p] + ubase;
                    uint32_t t[4];
                    ldsm4(t, stage + AT + (bo ^ ((bo >> 3) & 0x70)));
                    bf[nxt][2 * p][0] = t[0]; bf[nxt][2 * p][1] = t[1];
                    bf[nxt][2 * p + 1][0] = t[2]; bf[nxt][2 * p + 1][1] = t[3];
                }
            }
#pragma unroll
            for (int mi = 0; mi < 2; mi++)
#pragma unroll
                for (int nj = 0; nj < 4; nj++)
                    mma16816f16(acc[mi][nj], af[cur][mi], bf[cur][nj]);
        }
        __syncthreads();
        gissue(sb, c & 3, (c + NSTAGE) * BKC, bm, bn, tid);
    }

    // epilogue -> fp16 t1
#pragma unroll
    for (int mi = 0; mi < 2; mi++) {
        int r0 = bm + warp_m + mi * 16 + (lane >> 2);
        int r1 = r0 + 8;
#pragma unroll
        for (int nj = 0; nj < 4; nj++) {
            int col = bn + warp_n + nj * 8 + (lane & 3) * 2;
            if (r0 < N_NODES)
                *(__half2*)(g_t1 + (size_t)r0 * N_HID + col) =
                    __floats2half2_rn(acc[mi][nj][0], acc[mi][nj][1]);
            if (r1 < N_NODES)
                *(__half2*)(g_t1 + (size_t)r1 * N_HID + col) =
                    __floats2half2_rn(acc[mi][nj][2], acc[mi][nj][3]);
        }
    }
}

// ---------------- CSR build --------------------------------------------------
__global__ void hist_kernel(const int* __restrict__ rows, int E) {
    int i = blockIdx.x * blockDim.x + threadIdx.x;
    if (i < E) atomicAdd(&g_counts[rows[i]], 1);
}

// thread-coarsened shuffle scan; zeroes g_counts and seeds g_cursor
#define SCAN_PER 15
__global__ void __launch_bounds__(1024) scan_kernel() {
    __shared__ int wsum[32];
    int tid = threadIdx.x;
    int lane = tid & 31, w = tid >> 5;
    int base = tid * SCAN_PER;
    int c[SCAN_PER];
    int sum = 0;
#pragma unroll
    for (int i = 0; i < SCAN_PER; i++) {
        int g = base + i;
        c[i] = (g < N_NODES) ? g_counts[g] : 0;
        if (g < N_NODES) g_counts[g] = 0;
        sum += c[i];
    }
    int incl = sum;
#pragma unroll
    for (int off = 1; off < 32; off <<= 1) {
        int t = __shfl_up_sync(0xFFFFFFFFu, incl, off);
        if (lane >= off) incl += t;
    }
    if (lane == 31) wsum[w] = incl;
    __syncthreads();
    if (w == 0) {
        int v = wsum[lane];
#pragma unroll
        for (int off = 1; off < 32; off <<= 1) {
            int t = __shfl_up_sync(0xFFFFFFFFu, v, off);
            if (lane >= off) v += t;
        }
        wsum[lane] = v;
    }
    __syncthreads();
    int run = (w > 0 ? wsum[w - 1] : 0) + incl - sum;   // exclusive prefix
    if (tid == 0) g_rowptr[0] = 0;
#pragma unroll
    for (int i = 0; i < SCAN_PER; i++) {
        int g = base + i;
        if (g < N_NODES) {
            g_cursor[g] = run;
            run += c[i];
            g_rowptr[g + 1] = run;
        }
    }
}

__global__ void scatter_kernel(const int* __restrict__ rows, const int* __restrict__ cols,
                               const float* __restrict__ vals, int E) {
    int i = blockIdx.x * blockDim.x + threadIdx.x;
    if (i < E) {
        int r = rows[i];
        int p = atomicAdd(&g_cursor[r], 1);
        g_ecol[p] = cols[i];
        g_eval[p] = vals[i];
    }
}

// ---------------- SpMM1 (+b1, relu): h1 = relu(A @ t1 + b1) -> fp16 ----------
__global__ __launch_bounds__(128) void spmm1_kernel(const float* __restrict__ b1) {
    int r = blockIdx.x;
    int tid = threadIdx.x;
    int s = g_rowptr[r], e = g_rowptr[r + 1];
    float4 acc0 = make_float4(0.f, 0.f, 0.f, 0.f);
    float4 acc1 = make_float4(0.f, 0.f, 0.f, 0.f);
    int i = s;
    for (; i + 1 < e; i += 2) {
        int   c0 = g_ecol[i],     c1 = g_ecol[i + 1];
        float v0 = g_eval[i],     v1 = g_eval[i + 1];
        uint2 r0 = __ldg((const uint2*)(g_t1 + (size_t)c0 * N_HID) + tid);
        uint2 r1 = __ldg((const uint2*)(g_t1 + (size_t)c1 * N_HID) + tid);
        float2 p0 = __half22float2(*(__half2*)&r0.x), p1 = __half22float2(*(__half2*)&r0.y);
        float2 q0 = __half22float2(*(__half2*)&r1.x), q1 = __half22float2(*(__half2*)&r1.y);
        acc0.x += v0 * p0.x; acc0.y += v0 * p0.y; acc0.z += v0 * p1.x; acc0.w += v0 * p1.y;
        acc1.x += v1 * q0.x; acc1.y += v1 * q0.y; acc1.z += v1 * q1.x; acc1.w += v1 * q1.y;
    }
    if (i < e) {
        int   c = g_ecol[i];
        float v = g_eval[i];
        uint2 r0 = __ldg((const uint2*)(g_t1 + (size_t)c * N_HID) + tid);
        float2 p0 = __half22float2(*(__half2*)&r0.x), p1 = __half22float2(*(__half2*)&r0.y);
        acc0.x += v * p0.x; acc0.y += v * p0.y; acc0.z += v * p1.x; acc0.w += v * p1.y;
    }
    float4 bb = ((const float4*)b1)[tid];
    float hx = fmaxf(acc0.x + acc1.x + bb.x, 0.f);
    float hy = fmaxf(acc0.y + acc1.y + bb.y, 0.f);
    float hz = fmaxf(acc0.z + acc1.z + bb.z, 0.f);
    float hw = fmaxf(acc0.w + acc1.w + bb.w, 0.f);
    uint2 o;
    *(__half2*)&o.x = __floats2half2_rn(hx, hy);
    *(__half2*)&o.y = __floats2half2_rn(hz, hw);
    ((uint2*)(g_h1 + (size_t)r * N_HID))[tid] = o;
}

// ---------------- GEMM2: g_t2 = h1_fp16[M,512] @ W2[512,16] ------------------
__global__ __launch_bounds__(256) void gemm2_kernel(const float* __restrict__ W2) {
    __shared__ float Ws[N_HID * N_CLASS];
    for (int i = threadIdx.x; i < N_HID * N_CLASS; i += blockDim.x) Ws[i] = W2[i];
    __syncthreads();
    int row = blockIdx.x * 16 + (threadIdx.x >> 4);
    int c = threadIdx.x & 15;
    if (row >= N_NODES) return;
    const uint2* a4 = (const uint2*)(g_h1 + (size_t)row * N_HID);
    float acc = 0.f;
#pragma unroll 4
    for (int k = 0; k < N_HID / 4; k++) {
        uint2 r = a4[k];
        float2 a0 = __half22float2(*(__half2*)&r.x);
        float2 a1 = __half22float2(*(__half2*)&r.y);
        acc += a0.x * Ws[(4 * k + 0) * N_CLASS + c];
        acc += a0.y * Ws[(4 * k + 1) * N_CLASS + c];
        acc += a1.x * Ws[(4 * k + 2) * N_CLASS + c];
        acc += a1.y * Ws[(4 * k + 3) * N_CLASS + c];
    }
    g_t2[(size_t)row * N_CLASS + c] = acc;
}

// ---------------- SpMM2 (+b2): out = A @ g_t2 + b2 ---------------------------
__global__ void spmm2_kernel(const float* __restrict__ b2, float* __restrict__ out) {
    int w = (blockIdx.x * blockDim.x + threadIdx.x) >> 5;
    int lane = threadIdx.x & 31;
    if (w >= N_NODES) return;
    int s = g_rowptr[w], e = g_rowptr[w + 1];
    float acc = 0.f;
    for (int i = s; i < e; i++) {
        int   c = g_ecol[i];
        float v = g_eval[i];
        if (lane < N_CLASS) acc += v * __ldg(g_t2 + (size_t)c * N_CLASS + lane);
    }
    if (lane < N_CLASS) out[(size_t)w * N_CLASS + lane] = acc + b2[lane];
}

// ---------------- launch -----------------------------------------------------
extern "C" void kernel_launch(void* const* d_in, const int* in_sizes, int n_in,
                              void* d_out, int out_size) {
    const int*   x    = (const int*)d_in[0];
    const int*   rows = (const int*)d_in[1];
    const int*   cols = (const int*)d_in[2];
    const float* vals = (const float*)d_in[3];
    const float* emb  = (const float*)d_in[4];
    const float* W1   = (const float*)d_in[5];
    const float* b1   = (const float*)d_in[6];
    const float* W2   = (const float*)d_in[7];
    const float* b2   = (const float*)d_in[8];
    float* out = (float*)d_out;
    int E = in_sizes[1];

    cudaFuncSetAttribute(gemm1_mma_kernel,
                         cudaFuncAttributeMaxDynamicSharedMemorySize, GEMM_SMEM);

    detect_kernel<<<1, 256>>>(x, 512);
    embed_kernel<<<N_NODES, 256>>>(x, emb);
    convw1_kernel<<<(N_HID * IN_CH / 2 + 255) / 256, 256>>>(W1);
    gemm1_mma_kernel<<<dim3(N_HID / 64, M_PAD / 128), 256, GEMM_SMEM>>>();

    hist_kernel<<<(E + 255) / 256, 256>>>(rows, E);
    scan_kernel<<<1, 1024>>>();
    scatter_kernel<<<(E + 255) / 256, 256>>>(rows, cols, vals, E);

    spmm1_kernel<<<N_NODES, 128>>>(b1);
    gemm2_kernel<<<(N_NODES + 15) / 16, 256>>>(W2);
    spmm2_kernel<<<(N_NODES * 32 + 255) / 256, 256>>>(b2, out);
}

// round 12
// speedup vs baseline: 3.2899x; 1.0329x over previous
#include <cuda_runtime.h>
#include <cuda_fp16.h>
#include <cstdint>

#define N_NODES 15279
#define M_PAD   15360
#define E_EDGES 488928
#define IN_CH   1024
#define N_HID   512
#define N_CLASS 16
#define EMB_DIM 128

// ---------------- scratch (static device memory; no allocations) -------------
__device__ __half g_a[(size_t)M_PAD * IN_CH];            // 31.5 MB fp16 activations (pad rows stay 0)
__device__ __half g_b[(size_t)N_HID * IN_CH];            // 1 MB  (W1^T fp16)
__device__ __half g_t1[(size_t)N_NODES * N_HID];         // 15.7 MB h0@W1 (fp16)
__device__ __half g_h1[(size_t)N_NODES * N_HID];         // 15.7 MB relu(spmm+b1) (fp16)
__device__ float g_t2[(size_t)N_NODES * N_CLASS];        //  1.0 MB h1@W2
__device__ int   g_counts[N_NODES];                      // zero at load; re-zeroed by scan
__device__ int   g_rowptr[N_NODES + 1];
__device__ int   g_cursor[N_NODES];
__device__ int   g_ecol[E_EDGES];
__device__ float g_eval[E_EDGES];

// ---------------- PTX helpers (sm_80+ features only) -------------------------
static __device__ __forceinline__ uint32_t s2u(const void* p) {
    uint32_t a;
    asm("{ .reg .u64 t; cvta.to.shared.u64 t, %1; cvt.u32.u64 %0, t; }" : "=r"(a) : "l"(p));
    return a;
}
static __device__ __forceinline__ void cp16(uint32_t dst, const void* src) {
    asm volatile("cp.async.cg.shared.global [%0], [%1], 16;" :: "r"(dst), "l"(src));
}
static __device__ __forceinline__ void cp_commit() {
    asm volatile("cp.async.commit_group;" ::: "memory");
}
static __device__ __forceinline__ void cp_wait2() {
    asm volatile("cp.async.wait_group 2;" ::: "memory");
}
static __device__ __forceinline__ void ldsm4(uint32_t* r, uint32_t a) {
    asm volatile("ldmatrix.sync.aligned.m8n8.x4.shared.b16 {%0,%1,%2,%3}, [%4];"
                 : "=r"(r[0]), "=r"(r[1]), "=r"(r[2]), "=r"(r[3]) : "r"(a));
}
static __device__ __forceinline__ void mma16816f16(float* d, const uint32_t* a, const uint32_t* b) {
    asm volatile(
        "mma.sync.aligned.m16n8k16.row.col.f32.f16.f16.f32 "
        "{%0,%1,%2,%3}, {%4,%5,%6,%7}, {%8,%9}, {%0,%1,%2,%3};"
        : "+f"(d[0]), "+f"(d[1]), "+f"(d[2]), "+f"(d[3])
        : "r"(a[0]), "r"(a[1]), "r"(a[2]), "r"(a[3]), "r"(b[0]), "r"(b[1]));
}

// ---------------- embedding lookup + relu -> fp16 (inline dtype detect) ------
// Dtype detection via the GLOBAL first 16 int32 words of x (in-bounds under
// both interpretations): int64 x has all odd (high) words zero; int32 x has
// 8 uniform [0,10000) indices there (all-zero prob ~1e-32).
__global__ void embed_kernel(const int* __restrict__ x32, const float* __restrict__ emb) {
    int n = blockIdx.x;
    int w = threadIdx.x >> 5, lane = threadIdx.x & 31;
    int j = lane & 15;
    int probe = __ldg(x32 + j);
    unsigned nz = __ballot_sync(0xFFFFFFFFu, (j & 1) && probe != 0);
    int idx;
    if (nz == 0) idx = __ldg(x32 + 2 * (n * 8 + w));   // int64: low word
    else         idx = __ldg(x32 + n * 8 + w);         // int32
    float4 v = ((const float4*)(emb + (size_t)idx * EMB_DIM))[lane];
    __half h[4];
    h[0] = __float2half(fmaxf(v.x, 0.f));
    h[1] = __float2half(fmaxf(v.y, 0.f));
    h[2] = __float2half(fmaxf(v.z, 0.f));
    h[3] = __float2half(fmaxf(v.w, 0.f));
    size_t off = (size_t)n * IN_CH + w * EMB_DIM + lane * 4;
    *(uint2*)(g_a + off) = *(uint2*)h;
}

// W1 [K=1024, N=512] fp32 -> B [N=512, K=1024] fp16 (transposed)
__global__ void convw1_kernel(const float* __restrict__ W1) {
    int i = blockIdx.x * blockDim.x + threadIdx.x;
    if (i >= N_HID * IN_CH / 2) return;
    int n = i / (IN_CH / 2);
    int k2 = (i % (IN_CH / 2)) * 2;
    float v0 = __ldg(W1 + (size_t)k2 * N_HID + n);
    float v1 = __ldg(W1 + (size_t)(k2 + 1) * N_HID + n);
    __half ph[2] = {__float2half(v0), __float2half(v1)};
    *(uint32_t*)(g_b + (size_t)n * IN_CH + k2) = *(uint32_t*)ph;
}

// ---------------- GEMM1 via mma.sync fp16: t1 = A @ B^T ----------------------
// block tile 128x128, BK=64, 8 warps (4Mx2N), warp tile 32x64,
// SW128-swizzled smem rows (128B), 3-stage cp.async pipeline, 2 CTAs/SM.
#define BKC 64
#define AT  16384                      // 128 rows x 64 fp16 x 2B
#define BT  16384                      // 128 rows x 64 fp16 x 2B
#define SSIZE (AT + BT)                // 32768
#define NSTAGE 3
#define GEMM_SMEM (NSTAGE * SSIZE)     // 98304

static __device__ __forceinline__ void gissue(uint32_t sb, int s, int k0,
                                              int bm, int bn, int tid) {
    if (k0 < IN_CH) {
        uint32_t stage = sb + s * SSIZE;
#pragma unroll
        for (int l = 0; l < 4; l++) {
            int unit = tid + l * 256;
            int r = unit >> 3, u = unit & 7;
            uint32_t bo = (r << 7) | (u << 4);
            uint32_t sw = bo ^ ((bo >> 3) & 0x70);
            cp16(stage + sw, g_a + (size_t)(bm + r) * IN_CH + k0 + u * 8);
            cp16(stage + AT + sw, g_b + (size_t)(bn + r) * IN_CH + k0 + u * 8);
        }
    }
    cp_commit();
}

__global__ void __launch_bounds__(256, 2) gemm1_mma_kernel() {
    extern __shared__ char smem[];
    uint32_t sb = s2u(smem);
    const int tid = threadIdx.x;
    const int wid = tid >> 5, lane = tid & 31;
    const int bm = blockIdx.y * 128, bn = blockIdx.x * 128;
    const int warp_m = (wid & 3) * 32;
    const int warp_n = (wid >> 2) * 64;

    uint32_t a_off[2], b_off[4];
#pragma unroll
    for (int mi = 0; mi < 2; mi++) {
        int row = warp_m + mi * 16 + ((lane >> 3) & 1) * 8 + (lane & 7);
        a_off[mi] = (uint32_t)((row << 7) | ((lane >> 4) << 4));
    }
#pragma unroll
    for (int p = 0; p < 4; p++) {
        int row = warp_n + p * 16 + (lane >> 4) * 8 + (lane & 7);
        b_off[p] = (uint32_t)((row << 7) | (((lane >> 3) & 1) << 4));
    }

    float acc[2][8][4];
#pragma unroll
    for (int mi = 0; mi < 2; mi++)
#pragma unroll
        for (int nj = 0; nj < 8; nj++)
#pragma unroll
            for (int q = 0; q < 4; q++) acc[mi][nj][q] = 0.f;

    gissue(sb, 0, 0, bm, bn, tid);
    gissue(sb, 1, BKC, bm, bn, tid);
    gissue(sb, 2, 2 * BKC, bm, bn, tid);

    const int NCHUNK = IN_CH / BKC;   // 16
    int stage_id = 0;
    for (int c = 0; c < NCHUNK; c++) {
        cp_wait2();
        __syncthreads();
        uint32_t stage = sb + stage_id * SSIZE;
#pragma unroll
        for (int kk = 0; kk < 4; kk++) {
            uint32_t ubase = (uint32_t)(kk * 2) << 4;
            uint32_t af[2][4];
#pragma unroll
            for (int mi = 0; mi < 2; mi++) {
                uint32_t bo = a_off[mi] + ubase;
                ldsm4(af[mi], stage + (bo ^ ((bo >> 3) & 0x70)));
            }
            uint32_t bf[8][2];
#pragma unroll
            for (int p = 0; p < 4; p++) {
                uint32_t bo = b_off[p] + ubase;
                uint32_t t[4];
                ldsm4(t, stage + AT + (bo ^ ((bo >> 3) & 0x70)));
                bf[2 * p][0] = t[0]; bf[2 * p][1] = t[1];
                bf[2 * p + 1][0] = t[2]; bf[2 * p + 1][1] = t[3];
            }
#pragma unroll
            for (int mi = 0; mi < 2; mi++)
#pragma unroll
                for (int nj = 0; nj < 8; nj++)
                    mma16816f16(acc[mi][nj], af[mi], bf[nj]);
        }
        __syncthreads();
        gissue(sb, stage_id, (c + NSTAGE) * BKC, bm, bn, tid);
        stage_id = (stage_id == NSTAGE - 1) ? 0 : stage_id + 1;
    }

    // epilogue -> fp16 t1
#pragma unroll
    for (int mi = 0; mi < 2; mi++) {
        int r0 = bm + warp_m + mi * 16 + (lane >> 2);
        int r1 = r0 + 8;
#pragma unroll
        for (int nj = 0; nj < 8; nj++) {
            int col = bn + warp_n + nj * 8 + (lane & 3) * 2;
            if (r0 < N_NODES)
                *(__half2*)(g_t1 + (size_t)r0 * N_HID + col) =
                    __floats2half2_rn(acc[mi][nj][0], acc[mi][nj][1]);
            if (r1 < N_NODES)
                *(__half2*)(g_t1 + (size_t)r1 * N_HID + col) =
                    __floats2half2_rn(acc[mi][nj][2], acc[mi][nj][3]);
        }
    }
}

// ---------------- CSR build --------------------------------------------------
__global__ void hist_kernel(const int* __restrict__ rows, int E) {
    int i = blockIdx.x * blockDim.x + threadIdx.x;
    if (i < E) atomicAdd(&g_counts[rows[i]], 1);
}

// thread-coarsened shuffle scan; zeroes g_counts and seeds g_cursor
#define SCAN_PER 15
__global__ void __launch_bounds__(1024) scan_kernel() {
    __shared__ int wsum[32];
    int tid = threadIdx.x;
    int lane = tid & 31, w = tid >> 5;
    int base = tid * SCAN_PER;
    int c[SCAN_PER];
    int sum = 0;
#pragma unroll
    for (int i = 0; i < SCAN_PER; i++) {
        int g = base + i;
        c[i] = (g < N_NODES) ? g_counts[g] : 0;
        if (g < N_NODES) g_counts[g] = 0;
        sum += c[i];
    }
    int incl = sum;
#pragma unroll
    for (int off = 1; off < 32; off <<= 1) {
        int t = __shfl_up_sync(0xFFFFFFFFu, incl, off);
        if (lane >= off) incl += t;
    }
    if (lane == 31) wsum[w] = incl;
    __syncthreads();
    if (w == 0) {
        int v = wsum[lane];
#pragma unroll
        for (int off = 1; off < 32; off <<= 1) {
            int t = __shfl_up_sync(0xFFFFFFFFu, v, off);
            if (lane >= off) v += t;
        }
        wsum[lane] = v;
    }
    __syncthreads();
    int run = (w > 0 ? wsum[w - 1] : 0) + incl - sum;   // exclusive prefix
    if (tid == 0) g_rowptr[0] = 0;
#pragma unroll
    for (int i = 0; i < SCAN_PER; i++) {
        int g = base + i;
        if (g < N_NODES) {
            g_cursor[g] = run;
            run += c[i];
            g_rowptr[g + 1] = run;
        }
    }
}

__global__ void scatter_kernel(const int* __restrict__ rows, const int* __restrict__ cols,
                               const float* __restrict__ vals, int E) {
    int i = blockIdx.x * blockDim.x + threadIdx.x;
    if (i < E) {
        int r = rows[i];
        int p = atomicAdd(&g_cursor[r], 1);
        g_ecol[p] = cols[i];
        g_eval[p] = vals[i];
    }
}

// ---------------- SpMM1 (+b1, relu): h1 = relu(A @ t1 + b1) -> fp16 ----------
__global__ __launch_bounds__(128) void spmm1_kernel(const float* __restrict__ b1) {
    int r = blockIdx.x;
    int tid = threadIdx.x;
    int s = g_rowptr[r], e = g_rowptr[r + 1];
    float4 acc0 = make_float4(0.f, 0.f, 0.f, 0.f);
    float4 acc1 = make_float4(0.f, 0.f, 0.f, 0.f);
    int i = s;
    for (; i + 1 < e; i += 2) {
        int   c0 = g_ecol[i],     c1 = g_ecol[i + 1];
        float v0 = g_eval[i],     v1 = g_eval[i + 1];
        uint2 r0 = __ldg((const uint2*)(g_t1 + (size_t)c0 * N_HID) + tid);
        uint2 r1 = __ldg((const uint2*)(g_t1 + (size_t)c1 * N_HID) + tid);
        float2 p0 = __half22float2(*(__half2*)&r0.x), p1 = __half22float2(*(__half2*)&r0.y);
        float2 q0 = __half22float2(*(__half2*)&r1.x), q1 = __half22float2(*(__half2*)&r1.y);
        acc0.x += v0 * p0.x; acc0.y += v0 * p0.y; acc0.z += v0 * p1.x; acc0.w += v0 * p1.y;
        acc1.x += v1 * q0.x; acc1.y += v1 * q0.y; acc1.z += v1 * q1.x; acc1.w += v1 * q1.y;
    }
    if (i < e) {
        int   c = g_ecol[i];
        float v = g_eval[i];
        uint2 r0 = __ldg((const uint2*)(g_t1 + (size_t)c * N_HID) + tid);
        float2 p0 = __half22float2(*(__half2*)&r0.x), p1 = __half22float2(*(__half2*)&r0.y);
        acc0.x += v * p0.x; acc0.y += v * p0.y; acc0.z += v * p1.x; acc0.w += v * p1.y;
    }
    float4 bb = ((const float4*)b1)[tid];
    float hx = fmaxf(acc0.x + acc1.x + bb.x, 0.f);
    float hy = fmaxf(acc0.y + acc1.y + bb.y, 0.f);
    float hz = fmaxf(acc0.z + acc1.z + bb.z, 0.f);
    float hw = fmaxf(acc0.w + acc1.w + bb.w, 0.f);
    uint2 o;
    *(__half2*)&o.x = __floats2half2_rn(hx, hy);
    *(__half2*)&o.y = __floats2half2_rn(hz, hw);
    ((uint2*)(g_h1 + (size_t)r * N_HID))[tid] = o;
}

// ---------------- GEMM2: g_t2 = h1_fp16[M,512] @ W2[512,16] ------------------
__global__ __launch_bounds__(256) void gemm2_kernel(const float* __restrict__ W2) {
    __shared__ float Ws[N_HID * N_CLASS];
    for (int i = threadIdx.x; i < N_HID * N_CLASS; i += blockDim.x) Ws[i] = W2[i];
    __syncthreads();
    int row = blockIdx.x * 16 + (threadIdx.x >> 4);
    int c = threadIdx.x & 15;
    if (row >= N_NODES) return;
    const uint2* a4 = (const uint2*)(g_h1 + (size_t)row * N_HID);
    float acc = 0.f;
#pragma unroll 4
    for (int k = 0; k < N_HID / 4; k++) {
        uint2 r = a4[k];
        float2 a0 = __half22float2(*(__half2*)&r.x);
        float2 a1 = __half22float2(*(__half2*)&r.y);
        acc += a0.x * Ws[(4 * k + 0) * N_CLASS + c];
        acc += a0.y * Ws[(4 * k + 1) * N_CLASS + c];
        acc += a1.x * Ws[(4 * k + 2) * N_CLASS + c];
        acc += a1.y * Ws[(4 * k + 3) * N_CLASS + c];
    }
    g_t2[(size_t)row * N_CLASS + c] = acc;
}

// ---------------- SpMM2 (+b2): out = A @ g_t2 + b2 ---------------------------
__global__ void spmm2_kernel(const float* __restrict__ b2, float* __restrict__ out) {
    int w = (blockIdx.x * blockDim.x + threadIdx.x) >> 5;
    int lane = threadIdx.x & 31;
    if (w >= N_NODES) return;
    int s = g_rowptr[w], e = g_rowptr[w + 1];
    float acc = 0.f;
    for (int i = s; i < e; i++) {
        int   c = g_ecol[i];
        float v = g_eval[i];
        if (lane < N_CLASS) acc += v * __ldg(g_t2 + (size_t)c * N_CLASS + lane);
    }
    if (lane < N_CLASS) out[(size_t)w * N_CLASS + lane] = acc + b2[lane];
}

// ---------------- launch -----------------------------------------------------
extern "C" void kernel_launch(void* const* d_in, const int* in_sizes, int n_in,
                              void* d_out, int out_size) {
    const int*   x    = (const int*)d_in[0];
    const int*   rows = (const int*)d_in[1];
    const int*   cols = (const int*)d_in[2];
    const float* vals = (const float*)d_in[3];
    const float* emb  = (const float*)d_in[4];
    const float* W1   = (const float*)d_in[5];
    const float* b1   = (const float*)d_in[6];
    const float* W2   = (const float*)d_in[7];
    const float* b2   = (const float*)d_in[8];
    float* out = (float*)d_out;
    int E = in_sizes[1];

    cudaFuncSetAttribute(gemm1_mma_kernel,
                         cudaFuncAttributeMaxDynamicSharedMemorySize, GEMM_SMEM);

    embed_kernel<<<N_NODES, 256>>>(x, emb);
    convw1_kernel<<<(N_HID * IN_CH / 2 + 255) / 256, 256>>>(W1);
    gemm1_mma_kernel<<<dim3(N_HID / 128, M_PAD / 128), 256, GEMM_SMEM>>>();

    hist_kernel<<<(E + 255) / 256, 256>>>(rows, E);
    scan_kernel<<<1, 1024>>>();
    scatter_kernel<<<(E + 255) / 256, 256>>>(rows, cols, vals, E);

    spmm1_kernel<<<N_NODES, 128>>>(b1);
    gemm2_kernel<<<(N_NODES + 15) / 16, 256>>>(W2);
    spmm2_kernel<<<(N_NODES * 32 + 255) / 256, 256>>>(b2, out);
}

// round 13
// speedup vs baseline: 3.6456x; 1.1081x over previous
#include <cuda_runtime.h>
#include <cuda_fp16.h>
#include <cstdint>

#define N_NODES 15279
#define M_PAD   15360
#define E_EDGES 488928
#define IN_CH   1024
#define N_HID   512
#define N_CLASS 16
#define EMB_DIM 128

// ---------------- scratch (static device memory; no allocations) -------------
__device__ __half g_a[(size_t)M_PAD * IN_CH];            // 31.5 MB fp16 activations (pad rows stay 0)
__device__ __half g_b[(size_t)N_HID * IN_CH];            // 1 MB  (W1^T fp16)
__device__ __half g_t1[(size_t)N_NODES * N_HID];         // 15.7 MB h0@W1 (fp16)
__device__ __half g_h1[(size_t)N_NODES * N_HID];         // 15.7 MB relu(spmm+b1) (fp16)
__device__ float g_t2[(size_t)N_NODES * N_CLASS];        //  1.0 MB h1@W2
__device__ int   g_counts[N_NODES];                      // zero at load; re-zeroed by scan
__device__ int   g_rowptr[N_NODES + 1];
__device__ int   g_cursor[N_NODES];
__device__ int   g_ecol[E_EDGES];
__device__ float g_eval[E_EDGES];

// ---------------- PTX helpers (sm_80+ features only) -------------------------
static __device__ __forceinline__ uint32_t s2u(const void* p) {
    uint32_t a;
    asm("{ .reg .u64 t; cvta.to.shared.u64 t, %1; cvt.u32.u64 %0, t; }" : "=r"(a) : "l"(p));
    return a;
}
static __device__ __forceinline__ void cp16(uint32_t dst, const void* src) {
    asm volatile("cp.async.cg.shared.global [%0], [%1], 16;" :: "r"(dst), "l"(src));
}
static __device__ __forceinline__ void cp_commit() {
    asm volatile("cp.async.commit_group;" ::: "memory");
}
static __device__ __forceinline__ void cp_wait2() {
    asm volatile("cp.async.wait_group 2;" ::: "memory");
}
static __device__ __forceinline__ void ldsm4(uint32_t* r, uint32_t a) {
    asm volatile("ldmatrix.sync.aligned.m8n8.x4.shared.b16 {%0,%1,%2,%3}, [%4];"
                 : "=r"(r[0]), "=r"(r[1]), "=r"(r[2]), "=r"(r[3]) : "r"(a));
}
static __device__ __forceinline__ void mma16816f16(float* d, const uint32_t* a, const uint32_t* b) {
    asm volatile(
        "mma.sync.aligned.m16n8k16.row.col.f32.f16.f16.f32 "
        "{%0,%1,%2,%3}, {%4,%5,%6,%7}, {%8,%9}, {%0,%1,%2,%3};"
        : "+f"(d[0]), "+f"(d[1]), "+f"(d[2]), "+f"(d[3])
        : "r"(a[0]), "r"(a[1]), "r"(a[2]), "r"(a[3]), "r"(b[0]), "r"(b[1]));
}

// ---------------- embedding lookup + relu -> fp16 (inline dtype detect) ------
// Dtype detection via the GLOBAL first 16 int32 words of x (in-bounds under
// both interpretations): int64 x has all odd (high) words zero; int32 x has
// 8 uniform [0,10000) indices there (all-zero prob ~1e-32).
__global__ void embed_kernel(const int* __restrict__ x32, const float* __restrict__ emb) {
    int n = blockIdx.x;
    int w = threadIdx.x >> 5, lane = threadIdx.x & 31;
    int j = lane & 15;
    int probe = __ldg(x32 + j);
    unsigned nz = __ballot_sync(0xFFFFFFFFu, (j & 1) && probe != 0);
    int idx;
    if (nz == 0) idx = __ldg(x32 + 2 * (n * 8 + w));   // int64: low word
    else         idx = __ldg(x32 + n * 8 + w);         // int32
    float4 v = ((const float4*)(emb + (size_t)idx * EMB_DIM))[lane];
    __half h[4];
    h[0] = __float2half(fmaxf(v.x, 0.f));
    h[1] = __float2half(fmaxf(v.y, 0.f));
    h[2] = __float2half(fmaxf(v.z, 0.f));
    h[3] = __float2half(fmaxf(v.w, 0.f));
    size_t off = (size_t)n * IN_CH + w * EMB_DIM + lane * 4;
    *(uint2*)(g_a + off) = *(uint2*)h;
}

// W1 [K=1024, N=512] fp32 -> B [N=512, K=1024] fp16 (transposed)
__global__ void convw1_kernel(const float* __restrict__ W1) {
    int i = blockIdx.x * blockDim.x + threadIdx.x;
    if (i >= N_HID * IN_CH / 2) return;
    int n = i / (IN_CH / 2);
    int k2 = (i % (IN_CH / 2)) * 2;
    float v0 = __ldg(W1 + (size_t)k2 * N_HID + n);
    float v1 = __ldg(W1 + (size_t)(k2 + 1) * N_HID + n);
    __half ph[2] = {__float2half(v0), __float2half(v1)};
    *(uint32_t*)(g_b + (size_t)n * IN_CH + k2) = *(uint32_t*)ph;
}

// ---------------- GEMM1 via mma.sync fp16: t1 = A @ B^T ----------------------
// block tile 128x128, BK=64, 8 warps (4Mx2N), warp tile 32x64,
// SW128-swizzled smem rows (128B), 3-stage cp.async pipeline, 2 CTAs/SM.
#define BKC 64
#define AT  16384                      // 128 rows x 64 fp16 x 2B
#define BT  16384                      // 128 rows x 64 fp16 x 2B
#define SSIZE (AT + BT)                // 32768
#define NSTAGE 3
#define GEMM_SMEM (NSTAGE * SSIZE)     // 98304

static __device__ __forceinline__ void gissue(uint32_t sb, int s, int k0,
                                              int bm, int bn, int tid) {
    if (k0 < IN_CH) {
        uint32_t stage = sb + s * SSIZE;
#pragma unroll
        for (int l = 0; l < 4; l++) {
            int unit = tid + l * 256;
            int r = unit >> 3, u = unit & 7;
            uint32_t bo = (r << 7) | (u << 4);
            uint32_t sw = bo ^ ((bo >> 3) & 0x70);
            cp16(stage + sw, g_a + (size_t)(bm + r) * IN_CH + k0 + u * 8);
            cp16(stage + AT + sw, g_b + (size_t)(bn + r) * IN_CH + k0 + u * 8);
        }
    }
    cp_commit();
}

__global__ void __launch_bounds__(256, 2) gemm1_mma_kernel() {
    extern __shared__ char smem[];
    uint32_t sb = s2u(smem);
    const int tid = threadIdx.x;
    const int wid = tid >> 5, lane = tid & 31;
    const int bm = blockIdx.y * 128, bn = blockIdx.x * 128;
    const int warp_m = (wid & 3) * 32;
    const int warp_n = (wid >> 2) * 64;

    uint32_t a_off[2], b_off[4];
#pragma unroll
    for (int mi = 0; mi < 2; mi++) {
        int row = warp_m + mi * 16 + ((lane >> 3) & 1) * 8 + (lane & 7);
        a_off[mi] = (uint32_t)((row << 7) | ((lane >> 4) << 4));
    }
#pragma unroll
    for (int p = 0; p < 4; p++) {
        int row = warp_n + p * 16 + (lane >> 4) * 8 + (lane & 7);
        b_off[p] = (uint32_t)((row << 7) | (((lane >> 3) & 1) << 4));
    }

    float acc[2][8][4];
#pragma unroll
    for (int mi = 0; mi < 2; mi++)
#pragma unroll
        for (int nj = 0; nj < 8; nj++)
#pragma unroll
            for (int q = 0; q < 4; q++) acc[mi][nj][q] = 0.f;

    gissue(sb, 0, 0, bm, bn, tid);
    gissue(sb, 1, BKC, bm, bn, tid);
    gissue(sb, 2, 2 * BKC, bm, bn, tid);

    const int NCHUNK = IN_CH / BKC;   // 16
    int stage_id = 0;
    for (int c = 0; c < NCHUNK; c++) {
        cp_wait2();
        __syncthreads();
        uint32_t stage = sb + stage_id * SSIZE;
#pragma unroll
        for (int kk = 0; kk < 4; kk++) {
            uint32_t ubase = (uint32_t)(kk * 2) << 4;
            uint32_t af[2][4];
#pragma unroll
            for (int mi = 0; mi < 2; mi++) {
                uint32_t bo = a_off[mi] + ubase;
                ldsm4(af[mi], stage + (bo ^ ((bo >> 3) & 0x70)));
            }
            uint32_t bf[8][2];
#pragma unroll
            for (int p = 0; p < 4; p++) {
                uint32_t bo = b_off[p] + ubase;
                uint32_t t[4];
                ldsm4(t, stage + AT + (bo ^ ((bo >> 3) & 0x70)));
                bf[2 * p][0] = t[0]; bf[2 * p][1] = t[1];
                bf[2 * p + 1][0] = t[2]; bf[2 * p + 1][1] = t[3];
            }
#pragma unroll
            for (int mi = 0; mi < 2; mi++)
#pragma unroll
                for (int nj = 0; nj < 8; nj++)
                    mma16816f16(acc[mi][nj], af[mi], bf[nj]);
        }
        __syncthreads();
        gissue(sb, stage_id, (c + NSTAGE) * BKC, bm, bn, tid);
        stage_id = (stage_id == NSTAGE - 1) ? 0 : stage_id + 1;
    }

    // epilogue -> fp16 t1
#pragma unroll
    for (int mi = 0; mi < 2; mi++) {
        int r0 = bm + warp_m + mi * 16 + (lane >> 2);
        int r1 = r0 + 8;
#pragma unroll
        for (int nj = 0; nj < 8; nj++) {
            int col = bn + warp_n + nj * 8 + (lane & 3) * 2;
            if (r0 < N_NODES)
                *(__half2*)(g_t1 + (size_t)r0 * N_HID + col) =
                    __floats2half2_rn(acc[mi][nj][0], acc[mi][nj][1]);
            if (r1 < N_NODES)
                *(__half2*)(g_t1 + (size_t)r1 * N_HID + col) =
                    __floats2half2_rn(acc[mi][nj][2], acc[mi][nj][3]);
        }
    }
}

// ---------------- CSR build --------------------------------------------------
__global__ void hist_kernel(const int* __restrict__ rows, int E) {
    int i = blockIdx.x * blockDim.x + threadIdx.x;
    if (i < E) atomicAdd(&g_counts[rows[i]], 1);
}

// thread-coarsened shuffle scan; zeroes g_counts and seeds g_cursor
#define SCAN_PER 15
__global__ void __launch_bounds__(1024) scan_kernel() {
    __shared__ int wsum[32];
    int tid = threadIdx.x;
    int lane = tid & 31, w = tid >> 5;
    int base = tid * SCAN_PER;
    int c[SCAN_PER];
    int sum = 0;
#pragma unroll
    for (int i = 0; i < SCAN_PER; i++) {
        int g = base + i;
        c[i] = (g < N_NODES) ? g_counts[g] : 0;
        if (g < N_NODES) g_counts[g] = 0;
        sum += c[i];
    }
    int incl = sum;
#pragma unroll
    for (int off = 1; off < 32; off <<= 1) {
        int t = __shfl_up_sync(0xFFFFFFFFu, incl, off);
        if (lane >= off) incl += t;
    }
    if (lane == 31) wsum[w] = incl;
    __syncthreads();
    if (w == 0) {
        int v = wsum[lane];
#pragma unroll
        for (int off = 1; off < 32; off <<= 1) {
            int t = __shfl_up_sync(0xFFFFFFFFu, v, off);
            if (lane >= off) v += t;
        }
        wsum[lane] = v;
    }
    __syncthreads();
    int run = (w > 0 ? wsum[w - 1] : 0) + incl - sum;   // exclusive prefix
    if (tid == 0) g_rowptr[0] = 0;
#pragma unroll
    for (int i = 0; i < SCAN_PER; i++) {
        int g = base + i;
        if (g < N_NODES) {
            g_cursor[g] = run;
            run += c[i];
            g_rowptr[g + 1] = run;
        }
    }
}

__global__ void scatter_kernel(const int* __restrict__ rows, const int* __restrict__ cols,
                               const float* __restrict__ vals, int E) {
    int i = blockIdx.x * blockDim.x + threadIdx.x;
    if (i < E) {
        int r = rows[i];
        int p = atomicAdd(&g_cursor[r], 1);
        g_ecol[p] = cols[i];
        g_eval[p] = vals[i];
    }
}

// ---------------- SpMM1 (+b1, relu): h1 = relu(A @ t1 + b1) -> fp16 ----------
__global__ __launch_bounds__(128) void spmm1_kernel(const float* __restrict__ b1) {
    int r = blockIdx.x;
    int tid = threadIdx.x;
    int s = g_rowptr[r], e = g_rowptr[r + 1];
    float4 acc0 = make_float4(0.f, 0.f, 0.f, 0.f);
    float4 acc1 = make_float4(0.f, 0.f, 0.f, 0.f);
    int i = s;
    for (; i + 1 < e; i += 2) {
        int   c0 = g_ecol[i],     c1 = g_ecol[i + 1];
        float v0 = g_eval[i],     v1 = g_eval[i + 1];
        uint2 r0 = __ldg((const uint2*)(g_t1 + (size_t)c0 * N_HID) + tid);
        uint2 r1 = __ldg((const uint2*)(g_t1 + (size_t)c1 * N_HID) + tid);
        float2 p0 = __half22float2(*(__half2*)&r0.x), p1 = __half22float2(*(__half2*)&r0.y);
        float2 q0 = __half22float2(*(__half2*)&r1.x), q1 = __half22float2(*(__half2*)&r1.y);
        acc0.x += v0 * p0.x; acc0.y += v0 * p0.y; acc0.z += v0 * p1.x; acc0.w += v0 * p1.y;
        acc1.x += v1 * q0.x; acc1.y += v1 * q0.y; acc1.z += v1 * q1.x; acc1.w += v1 * q1.y;
    }
    if (i < e) {
        int   c = g_ecol[i];
        float v = g_eval[i];
        uint2 r0 = __ldg((const uint2*)(g_t1 + (size_t)c * N_HID) + tid);
        float2 p0 = __half22float2(*(__half2*)&r0.x), p1 = __half22float2(*(__half2*)&r0.y);
        acc0.x += v * p0.x; acc0.y += v * p0.y; acc0.z += v * p1.x; acc0.w += v * p1.y;
    }
    float4 bb = ((const float4*)b1)[tid];
    float hx = fmaxf(acc0.x + acc1.x + bb.x, 0.f);
    float hy = fmaxf(acc0.y + acc1.y + bb.y, 0.f);
    float hz = fmaxf(acc0.z + acc1.z + bb.z, 0.f);
    float hw = fmaxf(acc0.w + acc1.w + bb.w, 0.f);
    uint2 o;
    *(__half2*)&o.x = __floats2half2_rn(hx, hy);
    *(__half2*)&o.y = __floats2half2_rn(hz, hw);
    ((uint2*)(g_h1 + (size_t)r * N_HID))[tid] = o;
}

// ---------------- GEMM2: g_t2 = h1_fp16[M,512] @ W2[512,16] ------------------
__global__ __launch_bounds__(256) void gemm2_kernel(const float* __restrict__ W2) {
    __shared__ float Ws[N_HID * N_CLASS];
    for (int i = threadIdx.x; i < N_HID * N_CLASS; i += blockDim.x) Ws[i] = W2[i];
    __syncthreads();
    int row = blockIdx.x * 16 + (threadIdx.x >> 4);
    int c = threadIdx.x & 15;
    if (row >= N_NODES) return;
    const uint2* a4 = (const uint2*)(g_h1 + (size_t)row * N_HID);
    float acc = 0.f;
#pragma unroll 4
    for (int k = 0; k < N_HID / 4; k++) {
        uint2 r = a4[k];
        float2 a0 = __half22float2(*(__half2*)&r.x);
        float2 a1 = __half22float2(*(__half2*)&r.y);
        acc += a0.x * Ws[(4 * k + 0) * N_CLASS + c];
        acc += a0.y * Ws[(4 * k + 1) * N_CLASS + c];
        acc += a1.x * Ws[(4 * k + 2) * N_CLASS + c];
        acc += a1.y * Ws[(4 * k + 3) * N_CLASS + c];
    }
    g_t2[(size_t)row * N_CLASS + c] = acc;
}

// ---------------- SpMM2 (+b2): out = A @ g_t2 + b2 ---------------------------
__global__ void spmm2_kernel(const float* __restrict__ b2, float* __restrict__ out) {
    int w = (blockIdx.x * blockDim.x + threadIdx.x) >> 5;
    int lane = threadIdx.x & 31;
    if (w >= N_NODES) return;
    int s = g_rowptr[w], e = g_rowptr[w + 1];
    float acc = 0.f;
    for (int i = s; i < e; i++) {
        int   c = g_ecol[i];
        float v = g_eval[i];
        if (lane < N_CLASS) acc += v * __ldg(g_t2 + (size_t)c * N_CLASS + lane);
    }
    if (lane < N_CLASS) out[(size_t)w * N_CLASS + lane] = acc + b2[lane];
}

// ---------------- launch: fork CSR chain onto a side stream -------------------
extern "C" void kernel_launch(void* const* d_in, const int* in_sizes, int n_in,
                              void* d_out, int out_size) {
    const int*   x    = (const int*)d_in[0];
    const int*   rows = (const int*)d_in[1];
    const int*   cols = (const int*)d_in[2];
    const float* vals = (const float*)d_in[3];
    const float* emb  = (const float*)d_in[4];
    const float* W1   = (const float*)d_in[5];
    const float* b1   = (const float*)d_in[6];
    const float* W2   = (const float*)d_in[7];
    const float* b2   = (const float*)d_in[8];
    float* out = (float*)d_out;
    int E = in_sizes[1];

    // one-time host-side resource creation (no device memory; happens on the
    // first — non-captured — correctness call; identical captured work per call)
    static cudaStream_t s_side = nullptr;
    static cudaEvent_t  ev_fork = nullptr, ev_join = nullptr;
    if (s_side == nullptr) {
        cudaStreamCreateWithFlags(&s_side, cudaStreamNonBlocking);
        cudaEventCreateWithFlags(&ev_fork, cudaEventDisableTiming);
        cudaEventCreateWithFlags(&ev_join, cudaEventDisableTiming);
    }

    cudaFuncSetAttribute(gemm1_mma_kernel,
                         cudaFuncAttributeMaxDynamicSharedMemorySize, GEMM_SMEM);

    // fork: CSR chain on side stream, GEMM chain on main stream
    cudaEventRecord(ev_fork, 0);
    cudaStreamWaitEvent(s_side, ev_fork, 0);

    hist_kernel<<<(E + 255) / 256, 256, 0, s_side>>>(rows, E);
    scan_kernel<<<1, 1024, 0, s_side>>>();
    scatter_kernel<<<(E + 255) / 256, 256, 0, s_side>>>(rows, cols, vals, E);
    cudaEventRecord(ev_join, s_side);

    embed_kernel<<<N_NODES, 256>>>(x, emb);
    convw1_kernel<<<(N_HID * IN_CH / 2 + 255) / 256, 256>>>(W1);
    gemm1_mma_kernel<<<dim3(N_HID / 128, M_PAD / 128), 256, GEMM_SMEM>>>();

    // join: sparse kernels need both chains
    cudaStreamWaitEvent(0, ev_join, 0);

    spmm1_kernel<<<N_NODES, 128>>>(b1);
    gemm2_kernel<<<(N_NODES + 15) / 16, 256>>>(W2);
    spmm2_kernel<<<(N_NODES * 32 + 255) / 256, 256>>>(b2, out);
}